// round 13
// baseline (speedup 1.0000x reference)
#include <cuda_runtime.h>
#include <cuda_bf16.h>
#include <cuda_fp16.h>
#include <cstdint>
#include <cstddef>

#define NTOK 8192
#define CD   512
#define NH   8

#define BM 128
#define BN 128
#define BK 32
#define KPW 20
#define MAT_WORDS (128 * KPW)          // 2560
#define STAGE_WORDS_V0 (4 * MAT_WORDS)
#define SMEM_V0 (2 * STAGE_WORDS_V0 * 4)     // 81920
#define STAGE_WORDS_V2 (2 * MAT_WORDS)
#define SMEM_V2 (2 * STAGE_WORDS_V2 * 4)     // 40960

// big-warp-tile sim kernel: CTA 256x128, warp tile 64x64, 1 CTA/SM
#define AMW (256 * KPW)                 // 5120 words per A matrix
#define BMW (128 * KPW)                 // 2560 words per B matrix
#define STW_BIG (2 * AMW + 2 * BMW)     // 15360 words
#define SMEM_BIG (2 * STW_BIG * 4)      // 122880 bytes

typedef __nv_bfloat16 bf16;
typedef __half fp16;

// ---------------- scratch ----------------------------------------------------
__device__ bf16 g_xhi[NTOK*CD],  g_xlo[NTOK*CD];
__device__ bf16 g_WtThi[CD*CD],  g_WtTlo[CD*CD];
__device__ bf16 g_WpThi[CD*CD],  g_WpTlo[CD*CD];
__device__ bf16 g_Qhi[NTOK*CD],  g_Qlo[NTOK*CD];
__device__ bf16 g_Khi[NTOK*CD],  g_Klo[NTOK*CD];
__device__ fp16 g_xTh[CD*NTOK];
__device__ fp16 g_WkTh[NH*CD*CD];
__device__ fp16 g_Phi[(size_t)NTOK*NTOK];
__device__ fp16 g_Yh[NTOK*CD];
__device__ float g_S[(size_t)NTOK*NTOK];
__device__ fp16 g_Z[(size_t)NH*NTOK*CD];

// ---------------- helpers ----------------------------------------------------
__device__ __forceinline__ uint32_t smem_u32(const void* p) {
    uint32_t a;
    asm("{ .reg .u64 t; cvta.to.shared.u64 t, %1; cvt.u32.u64 %0, t; }" : "=r"(a) : "l"(p));
    return a;
}
__device__ __forceinline__ void cp16(uint32_t d, const void* s) {
    asm volatile("cp.async.cg.shared.global [%0], [%1], 16;" :: "r"(d), "l"(s));
}
__device__ __forceinline__ void cp_commit() { asm volatile("cp.async.commit_group;"); }
__device__ __forceinline__ void cp_wait1()  { asm volatile("cp.async.wait_group 1;"); }

__device__ __forceinline__ void ldsm4(uint32_t& r0, uint32_t& r1, uint32_t& r2, uint32_t& r3,
                                      uint32_t addr) {
    asm volatile("ldmatrix.sync.aligned.m8n8.x4.shared.b16 {%0,%1,%2,%3}, [%4];"
                 : "=r"(r0), "=r"(r1), "=r"(r2), "=r"(r3) : "r"(addr));
}
__device__ __forceinline__ void mma_bf(float& c0, float& c1, float& c2, float& c3,
                                       uint32_t a0, uint32_t a1, uint32_t a2, uint32_t a3,
                                       uint32_t b0, uint32_t b1) {
    asm volatile(
        "mma.sync.aligned.m16n8k16.row.col.f32.bf16.bf16.f32 "
        "{%0,%1,%2,%3}, {%4,%5,%6,%7}, {%8,%9}, {%0,%1,%2,%3};"
        : "+f"(c0), "+f"(c1), "+f"(c2), "+f"(c3)
        : "r"(a0), "r"(a1), "r"(a2), "r"(a3), "r"(b0), "r"(b1));
}
__device__ __forceinline__ void mma_fp(float& c0, float& c1, float& c2, float& c3,
                                       uint32_t a0, uint32_t a1, uint32_t a2, uint32_t a3,
                                       uint32_t b0, uint32_t b1) {
    asm volatile(
        "mma.sync.aligned.m16n8k16.row.col.f32.f16.f16.f32 "
        "{%0,%1,%2,%3}, {%4,%5,%6,%7}, {%8,%9}, {%0,%1,%2,%3};"
        : "+f"(c0), "+f"(c1), "+f"(c2), "+f"(c3)
        : "r"(a0), "r"(a1), "r"(a2), "r"(a3), "r"(b0), "r"(b1));
}

// ---------------- sim GEMM, 64x64 warp tiles: S[8192,8192] = A @ B^T ---------
// A = Qhi/Qlo, B = Khi/Klo (bf16x3). CTA 256x128, 8 warps (4m x 2n), fp32 out.
__global__ __launch_bounds__(256, 1)
void gemm_sim(const uint16_t* __restrict__ Ahi, const uint16_t* __restrict__ Alo,
              const uint16_t* __restrict__ Bhi, const uint16_t* __restrict__ Blo,
              float* __restrict__ C)
{
    extern __shared__ float sm[];
    const int K = CD, N = NTOK;
    const int tid  = threadIdx.x;
    const int wid  = tid >> 5, lane = tid & 31;
    const int gid  = lane >> 2, tig = lane & 3;
    const int wm   = wid & 3, wn = wid >> 2;      // 4 x 2 warps, tile 64x64

    const int mt_n = NTOK / 256, nt_n = N / BN;   // 32 x 64
    int tile = blockIdx.x;
    int npg  = 8 * nt_n;
    int grp  = tile / npg;
    int fm   = grp * 8;
    int gsz  = min(mt_n - fm, 8);
    int m_t  = fm + (tile % npg) % gsz;
    int n_t  = (tile % npg) / gsz;
    const int row0 = m_t * 256, col0 = n_t * BN;

    const uint32_t smb = smem_u32(sm);
    const int NC = K / BK;                        // 16

    const uint32_t laneA_off = (uint32_t)((wm * 64 + (lane & 15)) * KPW) * 4u
                             + ((lane >> 4) ? 16u : 0u);
    const uint32_t laneB_off = (uint32_t)((wn * 64 + (lane & 7) + ((lane & 16) ? 8 : 0)) * KPW) * 4u
                             + (((lane >> 3) & 1) ? 16u : 0u);

    auto load_chunk = [&](int c, int s) {
        const int k0 = c * BK;
        const uint32_t sbase = smb + (uint32_t)(s * STW_BIG) * 4u;
#pragma unroll
        for (int i = 0; i < 12; ++i) {            // 3072 cp16 total
            int id = i * 256 + tid;
            const uint16_t* src;
            int r, c4;
            uint32_t off;
            if (id < 2048) {                      // A: 2 mats x 256 rows x 4
                int mat = id >> 10;
                src = mat ? Alo : Ahi;
                r  = (id >> 2) & 255;
                c4 = id & 3;
                off = (uint32_t)(mat * AMW + r * KPW);
                r += row0;
            } else {                              // B: 2 mats x 128 rows x 4
                int x = id - 2048;
                int mat = x >> 9;
                src = mat ? Blo : Bhi;
                r  = (x >> 2) & 127;
                c4 = x & 3;
                off = (uint32_t)(2 * AMW + mat * BMW + r * KPW);
                r += col0;
            }
            cp16(sbase + off * 4u + (uint32_t)c4 * 16u,
                 src + (size_t)r * K + k0 + c4 * 8);
        }
    };

    float acc[4][8][4];
#pragma unroll
    for (int mt = 0; mt < 4; ++mt)
#pragma unroll
        for (int nt = 0; nt < 8; ++nt)
#pragma unroll
            for (int q = 0; q < 4; ++q) acc[mt][nt][q] = 0.f;

    load_chunk(0, 0); cp_commit();
    load_chunk(1, 1); cp_commit();

#pragma unroll 1
    for (int c = 0; c < NC; ++c) {
        const int s = c & 1;
        cp_wait1();
        __syncthreads();

        const uint32_t stage = smb + (uint32_t)(s * STW_BIG) * 4u;
        const uint32_t aAh = stage + laneA_off;
        const uint32_t aAl = aAh + (uint32_t)AMW * 4u;
        const uint32_t aBh = stage + 2u * (uint32_t)AMW * 4u + laneB_off;
        const uint32_t aBl = aBh + (uint32_t)BMW * 4u;

#pragma unroll
        for (int ks = 0; ks < 2; ++ks) {
            const uint32_t ko = (uint32_t)ks * 32u;
            uint32_t ah[4][4], al[4][4];
#pragma unroll
            for (int mt = 0; mt < 4; ++mt) {
                ldsm4(ah[mt][0], ah[mt][1], ah[mt][2], ah[mt][3],
                      aAh + (uint32_t)(mt * 16 * KPW) * 4u + ko);
                ldsm4(al[mt][0], al[mt][1], al[mt][2], al[mt][3],
                      aAl + (uint32_t)(mt * 16 * KPW) * 4u + ko);
            }
#pragma unroll
            for (int p = 0; p < 4; ++p) {
                uint32_t bh0, bh1, bh2, bh3, bl0, bl1, bl2, bl3;
                ldsm4(bh0, bh1, bh2, bh3, aBh + (uint32_t)(p * 16 * KPW) * 4u + ko);
                ldsm4(bl0, bl1, bl2, bl3, aBl + (uint32_t)(p * 16 * KPW) * 4u + ko);
#pragma unroll
                for (int mt = 0; mt < 4; ++mt) {
                    float* ae = acc[mt][2 * p];
                    float* ao = acc[mt][2 * p + 1];
                    mma_bf(ae[0], ae[1], ae[2], ae[3],
                           ah[mt][0], ah[mt][1], ah[mt][2], ah[mt][3], bh0, bh1);
                    mma_bf(ao[0], ao[1], ao[2], ao[3],
                           ah[mt][0], ah[mt][1], ah[mt][2], ah[mt][3], bh2, bh3);
                    mma_bf(ae[0], ae[1], ae[2], ae[3],
                           ah[mt][0], ah[mt][1], ah[mt][2], ah[mt][3], bl0, bl1);
                    mma_bf(ao[0], ao[1], ao[2], ao[3],
                           ah[mt][0], ah[mt][1], ah[mt][2], ah[mt][3], bl2, bl3);
                    mma_bf(ae[0], ae[1], ae[2], ae[3],
                           al[mt][0], al[mt][1], al[mt][2], al[mt][3], bh0, bh1);
                    mma_bf(ao[0], ao[1], ao[2], ao[3],
                           al[mt][0], al[mt][1], al[mt][2], al[mt][3], bh2, bh3);
                }
            }
        }
        __syncthreads();
        if (c + 2 < NC) load_chunk(c + 2, s);
        cp_commit();
    }

#pragma unroll
    for (int mt = 0; mt < 4; ++mt) {
#pragma unroll
        for (int nt = 0; nt < 8; ++nt) {
            int row = row0 + wm * 64 + mt * 16 + gid;
            int col = col0 + wn * 64 + nt * 8 + tig * 2;
            size_t ad0 = (size_t)row * N + col;
            size_t ad1 = (size_t)(row + 8) * N + col;
            float2 q0 = { acc[mt][nt][0], acc[mt][nt][1] };
            float2 q1 = { acc[mt][nt][2], acc[mt][nt][3] };
            *(float2*)(C + ad0) = q0;
            *(float2*)(C + ad1) = q1;
        }
    }
}

// ---------------- generic GEMM (proj / Y / Z), unchanged from R12 best -------
template<int V>
__global__ __launch_bounds__(256, 2)
void gemm_tc(const uint16_t* __restrict__ Ahi, const uint16_t* __restrict__ Alo,
             const uint16_t* __restrict__ Bhi, const uint16_t* __restrict__ Blo,
             int K, int N, void* __restrict__ C0v, void* __restrict__ C1v,
             const float* __restrict__ bias, int mode,
             size_t strB, size_t strBias, size_t strC)
{
    extern __shared__ float sm[];
    const int tid  = threadIdx.x;
    const int wid  = tid >> 5, lane = tid & 31;
    const int gid  = lane >> 2, tig = lane & 3;
    const int wm   = wid & 3, wn = wid >> 2;

    const int z = blockIdx.z;
    Bhi += (size_t)z * strB;
    if (V == 0) Blo += (size_t)z * strB;
    if (bias) bias += (size_t)z * strBias;
    const size_t zC = (size_t)z * strC;

    const int mt_n = NTOK / BM, nt_n = N / BN;
    int tile = blockIdx.x;
    int npg  = 8 * nt_n;
    int grp  = tile / npg;
    int fm   = grp * 8;
    int gsz  = min(mt_n - fm, 8);
    int m_t  = fm + (tile % npg) % gsz;
    int n_t  = (tile % npg) / gsz;
    const int row0 = m_t * BM, col0 = n_t * BN;

    const uint32_t smb = smem_u32(sm);
    const int NC = K / BK;
    const int STW = (V == 0) ? STAGE_WORDS_V0 : STAGE_WORDS_V2;
    const uint32_t bBase = ((V == 0) ? 2u : 1u) * (uint32_t)MAT_WORDS * 4u;

    const uint32_t laneA_off = (uint32_t)((wm * 32 + (lane & 15)) * KPW) * 4u
                             + ((lane >> 4) ? 16u : 0u);
    const uint32_t laneB_off = (uint32_t)((wn * 64 + (lane & 7) + ((lane & 16) ? 8 : 0)) * KPW) * 4u
                             + (((lane >> 3) & 1) ? 16u : 0u);

    auto load_chunk = [&](int c, int s) {
        const int k0 = c * BK;
        const uint32_t sbase = smb + (uint32_t)(s * STW) * 4u;
        const int NIT = (V == 0) ? 8 : 4;
#pragma unroll
        for (int i = 0; i < NIT; ++i) {
            int id  = i * 256 + tid;
            int mat;
            const uint16_t* src;
            int base;
            if (V == 0) {
                mat = id >> 9;
                src  = (mat == 0) ? Ahi : (mat == 1) ? Alo : (mat == 2) ? Bhi : Blo;
                base = (mat <= 1) ? row0 : col0;
            } else {
                mat = id >> 9;
                src  = mat ? Bhi : Ahi;
                base = mat ? col0 : row0;
            }
            int r   = (id >> 2) & 127;
            int c4  = id & 3;
            uint32_t dst = sbase + (uint32_t)(mat * MAT_WORDS + r * KPW) * 4u
                         + (uint32_t)c4 * 16u;
            cp16(dst, src + (size_t)(base + r) * K + k0 + c4 * 8);
        }
    };

    float acc[2][8][4];
#pragma unroll
    for (int mt = 0; mt < 2; ++mt)
#pragma unroll
        for (int nt = 0; nt < 8; ++nt)
#pragma unroll
            for (int q = 0; q < 4; ++q) acc[mt][nt][q] = 0.f;

    load_chunk(0, 0); cp_commit();
    if (NC > 1) load_chunk(1, 1);
    cp_commit();

#pragma unroll 1
    for (int c = 0; c < NC; ++c) {
        const int s = c & 1;
        cp_wait1();
        __syncthreads();

        const uint32_t stage = smb + (uint32_t)(s * STW) * 4u;
        const uint32_t aAh = stage + laneA_off;
        const uint32_t aAl = aAh + (uint32_t)MAT_WORDS * 4u;
        const uint32_t aBh = stage + bBase + laneB_off;
        const uint32_t aBl = aBh + (uint32_t)MAT_WORDS * 4u;

#pragma unroll
        for (int ks = 0; ks < 2; ++ks) {
            const uint32_t ko = (uint32_t)ks * 32u;
            uint32_t ah[2][4], al[2][4];
#pragma unroll
            for (int mt = 0; mt < 2; ++mt) {
                ldsm4(ah[mt][0], ah[mt][1], ah[mt][2], ah[mt][3],
                      aAh + (uint32_t)(mt * 16 * KPW) * 4u + ko);
                if (V == 0)
                    ldsm4(al[mt][0], al[mt][1], al[mt][2], al[mt][3],
                          aAl + (uint32_t)(mt * 16 * KPW) * 4u + ko);
            }
#pragma unroll
            for (int p = 0; p < 4; ++p) {
                uint32_t bh0, bh1, bh2, bh3;
                ldsm4(bh0, bh1, bh2, bh3, aBh + (uint32_t)(p * 16 * KPW) * 4u + ko);
                if (V == 0) {
                    uint32_t bl0, bl1, bl2, bl3;
                    ldsm4(bl0, bl1, bl2, bl3, aBl + (uint32_t)(p * 16 * KPW) * 4u + ko);
#pragma unroll
                    for (int mt = 0; mt < 2; ++mt) {
                        float* ae = acc[mt][2 * p];
                        float* ao = acc[mt][2 * p + 1];
                        mma_bf(ae[0], ae[1], ae[2], ae[3],
                               ah[mt][0], ah[mt][1], ah[mt][2], ah[mt][3], bh0, bh1);
                        mma_bf(ao[0], ao[1], ao[2], ao[3],
                               ah[mt][0], ah[mt][1], ah[mt][2], ah[mt][3], bh2, bh3);
                        mma_bf(ae[0], ae[1], ae[2], ae[3],
                               ah[mt][0], ah[mt][1], ah[mt][2], ah[mt][3], bl0, bl1);
                        mma_bf(ao[0], ao[1], ao[2], ao[3],
                               ah[mt][0], ah[mt][1], ah[mt][2], ah[mt][3], bl2, bl3);
                        mma_bf(ae[0], ae[1], ae[2], ae[3],
                               al[mt][0], al[mt][1], al[mt][2], al[mt][3], bh0, bh1);
                        mma_bf(ao[0], ao[1], ao[2], ao[3],
                               al[mt][0], al[mt][1], al[mt][2], al[mt][3], bh2, bh3);
                    }
                } else {
#pragma unroll
                    for (int mt = 0; mt < 2; ++mt) {
                        float* ae = acc[mt][2 * p];
                        float* ao = acc[mt][2 * p + 1];
                        mma_fp(ae[0], ae[1], ae[2], ae[3],
                               ah[mt][0], ah[mt][1], ah[mt][2], ah[mt][3], bh0, bh1);
                        mma_fp(ao[0], ao[1], ao[2], ao[3],
                               ah[mt][0], ah[mt][1], ah[mt][2], ah[mt][3], bh2, bh3);
                    }
                }
            }
        }
        __syncthreads();
        if (c + 2 < NC) load_chunk(c + 2, s);
        cp_commit();
    }

#pragma unroll
    for (int mt = 0; mt < 2; ++mt) {
#pragma unroll
        for (int nt = 0; nt < 8; ++nt) {
            int row = row0 + wm * 32 + mt * 16 + gid;
            int col = col0 + wn * 64 + nt * 8 + tig * 2;
            float v0 = acc[mt][nt][0], v1 = acc[mt][nt][1];
            float v2 = acc[mt][nt][2], v3 = acc[mt][nt][3];
            if (mode == 2 || mode == 3 || mode == 5) {
                float b0 = bias[col], b1 = bias[col + 1];
                v0 += b0; v1 += b1; v2 += b0; v3 += b1;
            }
            size_t ad0 = (size_t)row * N + col;
            size_t ad1 = (size_t)(row + 8) * N + col;
            if (mode == 2) {
                bf16* o0 = (bf16*)C0v + zC;
                bf16* o1 = (bf16*)C1v + zC;
                bf16 h0 = __float2bfloat16(v0), h1 = __float2bfloat16(v1);
                bf16 h2 = __float2bfloat16(v2), h3 = __float2bfloat16(v3);
                __nv_bfloat162 hh0 = { h0, h1 }, hh1 = { h2, h3 };
                __nv_bfloat162 ll0 = { __float2bfloat16(v0 - __bfloat162float(h0)),
                                       __float2bfloat16(v1 - __bfloat162float(h1)) };
                __nv_bfloat162 ll1 = { __float2bfloat16(v2 - __bfloat162float(h2)),
                                       __float2bfloat16(v3 - __bfloat162float(h3)) };
                *(__nv_bfloat162*)(o0 + ad0) = hh0;  *(__nv_bfloat162*)(o0 + ad1) = hh1;
                *(__nv_bfloat162*)(o1 + ad0) = ll0;  *(__nv_bfloat162*)(o1 + ad1) = ll1;
            } else if (mode == 4 || mode == 5) {
                fp16* o = (fp16*)C0v + zC;
                __half2 q0 = { __float2half(v0), __float2half(v1) };
                __half2 q1 = { __float2half(v2), __float2half(v3) };
                *(__half2*)(o + ad0) = q0;  *(__half2*)(o + ad1) = q1;
            } else {
                float* o = (float*)C0v + zC;
                float2 q0 = { v0, v1 }, q1 = { v2, v3 };
                *(float2*)(o + ad0) = q0;  *(float2*)(o + ad1) = q1;
            }
        }
    }
}

// ---------------- prep / softmax / reduce (unchanged) ------------------------
__global__ void split_transpose_x(const float* __restrict__ x, bf16* __restrict__ xhi,
                                  bf16* __restrict__ xlo, fp16* __restrict__ xTh)
{
    __shared__ float t[32][33];
    int c0 = blockIdx.x * 32, r0 = blockIdx.y * 32;
    int tx = threadIdx.x, ty = threadIdx.y;
#pragma unroll
    for (int i = 0; i < 4; ++i) {
        size_t ad = (size_t)(r0 + ty + i*8) * CD + c0 + tx;
        float v = x[ad];
        t[ty + i*8][tx] = v;
        bf16 h = __float2bfloat16(v);
        xhi[ad] = h;
        xlo[ad] = __float2bfloat16(v - __bfloat162float(h));
    }
    __syncthreads();
#pragma unroll
    for (int i = 0; i < 4; ++i) {
        size_t ad = (size_t)(c0 + ty + i*8) * NTOK + r0 + tx;
        xTh[ad] = __float2half(t[tx][ty + i*8]);
    }
}
__global__ void transpose_split_bf2(const float* __restrict__ W0, const float* __restrict__ W1,
                                    bf16* __restrict__ h0, bf16* __restrict__ l0,
                                    bf16* __restrict__ h1, bf16* __restrict__ l1)
{
    __shared__ float t[32][33];
    const float* s = blockIdx.z ? W1 : W0;
    bf16* oh = blockIdx.z ? h1 : h0;
    bf16* ol = blockIdx.z ? l1 : l0;
    int c0 = blockIdx.x * 32, r0 = blockIdx.y * 32;
    int tx = threadIdx.x, ty = threadIdx.y;
#pragma unroll
    for (int i = 0; i < 4; ++i)
        t[ty + i*8][tx] = s[(size_t)(r0 + ty + i*8) * CD + c0 + tx];
    __syncthreads();
#pragma unroll
    for (int i = 0; i < 4; ++i) {
        float v = t[tx][ty + i*8];
        bf16 h = __float2bfloat16(v);
        size_t ad = (size_t)(c0 + ty + i*8) * CD + r0 + tx;
        oh[ad] = h;
        ol[ad] = __float2bfloat16(v - __bfloat162float(h));
    }
}
__global__ void transpose_fp16(const float* __restrict__ src, fp16* __restrict__ dst,
                               int R, int C)
{
    __shared__ float t[32][33];
    const size_t bo = (size_t)blockIdx.z * R * C;
    const float* s = src + bo;
    fp16* o = dst + bo;
    int c0 = blockIdx.x * 32, r0 = blockIdx.y * 32;
    int tx = threadIdx.x, ty = threadIdx.y;
#pragma unroll
    for (int i = 0; i < 4; ++i)
        t[ty + i*8][tx] = s[(size_t)(r0 + ty + i*8) * C + c0 + tx];
    __syncthreads();
#pragma unroll
    for (int i = 0; i < 4; ++i) {
        size_t ad = (size_t)(c0 + ty + i*8) * R + r0 + tx;
        o[ad] = __float2half(t[tx][ty + i*8]);
    }
}
__device__ __forceinline__ float wmax(float v) {
#pragma unroll
    for (int o = 16; o > 0; o >>= 1) v = fmaxf(v, __shfl_xor_sync(0xffffffffu, v, o));
    return v;
}
__device__ __forceinline__ float wsum(float v) {
#pragma unroll
    for (int o = 16; o > 0; o >>= 1) v += __shfl_xor_sync(0xffffffffu, v, o);
    return v;
}
__global__ __launch_bounds__(256, 4)
void softmax_fp16(const float* __restrict__ S, fp16* __restrict__ Phi)
{
    const float* r = S + (size_t)blockIdx.x * NTOK;
    fp16* ph = Phi + (size_t)blockIdx.x * NTOK;
    const int tid = threadIdx.x;
    __shared__ float red[8];
    float v[32];
    float m = -3.4e38f;
#pragma unroll
    for (int i = 0; i < 32; ++i) { v[i] = r[i*256 + tid]; m = fmaxf(m, v[i]); }
    m = wmax(m);
    if ((tid & 31) == 0) red[tid >> 5] = m;
    __syncthreads();
    { float t = red[tid & 7];
      t = fmaxf(t, __shfl_xor_sync(0xffffffffu, t, 1));
      t = fmaxf(t, __shfl_xor_sync(0xffffffffu, t, 2));
      t = fmaxf(t, __shfl_xor_sync(0xffffffffu, t, 4)); m = t; }
    float s = 0.f;
#pragma unroll
    for (int i = 0; i < 32; ++i) { v[i] = __expf(v[i] - m); s += v[i]; }
    s = wsum(s);
    __syncthreads();
    if ((tid & 31) == 0) red[tid >> 5] = s;
    __syncthreads();
    { float t = red[tid & 7];
      t += __shfl_xor_sync(0xffffffffu, t, 1);
      t += __shfl_xor_sync(0xffffffffu, t, 2);
      t += __shfl_xor_sync(0xffffffffu, t, 4); s = t; }
    const float inv = 1.f / s;
#pragma unroll
    for (int i = 0; i < 32; ++i)
        ph[i*256 + tid] = __float2half(v[i] * inv);
}
__global__ void reduce_heads(const fp16* __restrict__ Z, float* __restrict__ out)
{
    const size_t n = (size_t)NTOK * CD / 4;
    const size_t str = n;
    const uint2* z = (const uint2*)Z;
    for (size_t i = (size_t)blockIdx.x * blockDim.x + threadIdx.x; i < n;
         i += (size_t)gridDim.x * blockDim.x) {
        float4 a = { 0.f, 0.f, 0.f, 0.f };
#pragma unroll
        for (int h = 0; h < NH; ++h) {
            uint2 u = z[h * str + i];
            float2 p0 = __half22float2(*(const __half2*)&u.x);
            float2 p1 = __half22float2(*(const __half2*)&u.y);
            a.x += fmaxf(p0.x, 0.f); a.y += fmaxf(p0.y, 0.f);
            a.z += fmaxf(p1.x, 0.f); a.w += fmaxf(p1.y, 0.f);
        }
        a.x *= 0.125f; a.y *= 0.125f; a.z *= 0.125f; a.w *= 0.125f;
        ((float4*)out)[i] = a;
    }
}

// ---------------- host -------------------------------------------------------
extern "C" void kernel_launch(void* const* d_in, const int* in_sizes, int n_in,
                              void* d_out, int out_size)
{
    (void)in_sizes; (void)n_in; (void)out_size;
    const float* x  = (const float*)d_in[0];
    const float* Wt = (const float*)d_in[1];
    const float* bt = (const float*)d_in[2];
    const float* Wp = (const float*)d_in[3];
    const float* bp = (const float*)d_in[4];
    const float* Wk = (const float*)d_in[5];
    const float* bk = (const float*)d_in[6];
    float* out = (float*)d_out;

    bf16 *xhi,*xlo,*WtThi,*WtTlo,*WpThi,*WpTlo,*Qhi,*Qlo,*Khi,*Klo;
    fp16 *xTh,*WkTh,*Phi,*Yh,*Z;
    float *S;
    cudaGetSymbolAddress((void**)&xhi, g_xhi);   cudaGetSymbolAddress((void**)&xlo, g_xlo);
    cudaGetSymbolAddress((void**)&WtThi, g_WtThi); cudaGetSymbolAddress((void**)&WtTlo, g_WtTlo);
    cudaGetSymbolAddress((void**)&WpThi, g_WpThi); cudaGetSymbolAddress((void**)&WpTlo, g_WpTlo);
    cudaGetSymbolAddress((void**)&Qhi, g_Qhi);   cudaGetSymbolAddress((void**)&Qlo, g_Qlo);
    cudaGetSymbolAddress((void**)&Khi, g_Khi);   cudaGetSymbolAddress((void**)&Klo, g_Klo);
    cudaGetSymbolAddress((void**)&xTh, g_xTh);   cudaGetSymbolAddress((void**)&WkTh, g_WkTh);
    cudaGetSymbolAddress((void**)&Phi, g_Phi);   cudaGetSymbolAddress((void**)&Yh, g_Yh);
    cudaGetSymbolAddress((void**)&S, g_S);       cudaGetSymbolAddress((void**)&Z, g_Z);

    cudaFuncSetAttribute(gemm_tc<0>, cudaFuncAttributeMaxDynamicSharedMemorySize, SMEM_V0);
    cudaFuncSetAttribute(gemm_tc<2>, cudaFuncAttributeMaxDynamicSharedMemorySize, SMEM_V2);
    cudaFuncSetAttribute(gemm_sim,  cudaFuncAttributeMaxDynamicSharedMemorySize, SMEM_BIG);

    // prep
    split_transpose_x<<<dim3(CD/32, NTOK/32), dim3(32, 8)>>>(x, xhi, xlo, xTh);
    transpose_split_bf2<<<dim3(CD/32, CD/32, 2), dim3(32, 8)>>>(
        Wt, Wp, WtThi, WtTlo, WpThi, WpTlo);
    transpose_fp16<<<dim3(CD/32, CD/32, NH), dim3(32, 8)>>>(Wk, WkTh, CD, CD);

    const int mt = NTOK / BM;            // 64
    // Q/K projections (bf16x3, split bf16 out)
    gemm_tc<0><<<mt * (CD/BN), 256, SMEM_V0>>>(
        (const uint16_t*)xhi, (const uint16_t*)xlo,
        (const uint16_t*)WtThi, (const uint16_t*)WtTlo,
        CD, CD, Qhi, Qlo, bt, 2, 0, 0, 0);
    gemm_tc<0><<<mt * (CD/BN), 256, SMEM_V0>>>(
        (const uint16_t*)xhi, (const uint16_t*)xlo,
        (const uint16_t*)WpThi, (const uint16_t*)WpTlo,
        CD, CD, Khi, Klo, bp, 2, 0, 0, 0);
    // sim (bf16x3, 64x64 warp tiles, fp32 out)
    gemm_sim<<<(NTOK/256) * (NTOK/BN), 256, SMEM_BIG>>>(
        (const uint16_t*)Qhi, (const uint16_t*)Qlo,
        (const uint16_t*)Khi, (const uint16_t*)Klo, S);
    // softmax -> fp16 P
    softmax_fp16<<<NTOK, 256>>>(S, Phi);
    // Y = P @ x (fp16 single pass, fp16 out)
    gemm_tc<2><<<mt * (CD/BN), 256, SMEM_V2>>>(
        (const uint16_t*)Phi, nullptr,
        (const uint16_t*)xTh, nullptr,
        NTOK, CD, Yh, nullptr, nullptr, 4, 0, 0, 0);
    // Z[h] = Y @ Wk[h]^T + bk[h] (fp16 single pass, fp16 out)
    gemm_tc<2><<<dim3(mt * (CD/BN), 1, NH), 256, SMEM_V2>>>(
        (const uint16_t*)Yh, nullptr,
        (const uint16_t*)WkTh, nullptr,
        CD, CD, Z, nullptr, bk, 5,
        (size_t)CD * CD, (size_t)CD, (size_t)NTOK * CD);
    // out = mean_h relu(Z)
    reduce_heads<<<512, 256>>>(Z, out);
}

// round 14
// speedup vs baseline: 1.1036x; 1.1036x over previous
#include <cuda_runtime.h>
#include <cuda_bf16.h>
#include <cuda_fp16.h>
#include <cstdint>
#include <cstddef>

#define NTOK 8192
#define CD   512
#define NH   8

#define BM 128
#define BN 128

typedef __nv_bfloat16 bf16;
typedef __half fp16;

// V0 (bf16x3): BK=32, KPW=20;  V2 (fp16 single): BK=64, KPW=36
#define SMEM_V0 (2 * 4 * (128 * 20) * 4)     // 81920
#define SMEM_V2 (2 * 2 * (128 * 36) * 4)     // 73728

// ---------------- scratch ----------------------------------------------------
__device__ bf16 g_xhi[NTOK*CD],  g_xlo[NTOK*CD];
__device__ bf16 g_WtThi[CD*CD],  g_WtTlo[CD*CD];
__device__ bf16 g_WpThi[CD*CD],  g_WpTlo[CD*CD];
__device__ bf16 g_Qhi[NTOK*CD],  g_Qlo[NTOK*CD];
__device__ bf16 g_Khi[NTOK*CD],  g_Klo[NTOK*CD];
__device__ fp16 g_xTh[CD*NTOK];
__device__ fp16 g_WkTh[NH*CD*CD];
__device__ fp16 g_Phi[(size_t)NTOK*NTOK];
__device__ fp16 g_Yh[NTOK*CD];
__device__ float g_S[(size_t)NTOK*NTOK];
__device__ fp16 g_Z[(size_t)NH*NTOK*CD];

// ---------------- helpers ----------------------------------------------------
__device__ __forceinline__ uint32_t smem_u32(const void* p) {
    uint32_t a;
    asm("{ .reg .u64 t; cvta.to.shared.u64 t, %1; cvt.u32.u64 %0, t; }" : "=r"(a) : "l"(p));
    return a;
}
__device__ __forceinline__ void cp16(uint32_t d, const void* s) {
    asm volatile("cp.async.cg.shared.global [%0], [%1], 16;" :: "r"(d), "l"(s));
}
__device__ __forceinline__ void cp_commit() { asm volatile("cp.async.commit_group;"); }
__device__ __forceinline__ void cp_wait1()  { asm volatile("cp.async.wait_group 1;"); }

__device__ __forceinline__ void ldsm4(uint32_t& r0, uint32_t& r1, uint32_t& r2, uint32_t& r3,
                                      uint32_t addr) {
    asm volatile("ldmatrix.sync.aligned.m8n8.x4.shared.b16 {%0,%1,%2,%3}, [%4];"
                 : "=r"(r0), "=r"(r1), "=r"(r2), "=r"(r3) : "r"(addr));
}
__device__ __forceinline__ void mma_bf(float& c0, float& c1, float& c2, float& c3,
                                       uint32_t a0, uint32_t a1, uint32_t a2, uint32_t a3,
                                       uint32_t b0, uint32_t b1) {
    asm volatile(
        "mma.sync.aligned.m16n8k16.row.col.f32.bf16.bf16.f32 "
        "{%0,%1,%2,%3}, {%4,%5,%6,%7}, {%8,%9}, {%0,%1,%2,%3};"
        : "+f"(c0), "+f"(c1), "+f"(c2), "+f"(c3)
        : "r"(a0), "r"(a1), "r"(a2), "r"(a3), "r"(b0), "r"(b1));
}
__device__ __forceinline__ void mma_fp(float& c0, float& c1, float& c2, float& c3,
                                       uint32_t a0, uint32_t a1, uint32_t a2, uint32_t a3,
                                       uint32_t b0, uint32_t b1) {
    asm volatile(
        "mma.sync.aligned.m16n8k16.row.col.f32.f16.f16.f32 "
        "{%0,%1,%2,%3}, {%4,%5,%6,%7}, {%8,%9}, {%0,%1,%2,%3};"
        : "+f"(c0), "+f"(c1), "+f"(c2), "+f"(c3)
        : "r"(a0), "r"(a1), "r"(a2), "r"(a3), "r"(b0), "r"(b1));
}

// ---------------- tensor GEMM: C[8192, N] = A @ B^T -------------------------
// V=0: bf16x3 (A hi/lo mats 0/1, B hi/lo mats 2/3), BK=32, KPW=20
// V=2: fp16 single-pass (A mat 0, B mat 1), BK=64, KPW=36
// mode 0: fp32->C0  2: +bias split bf16->C0/C1  3: +bias fp32->C0
// mode 4: fp16->C0  5: +bias fp16->C0
template<int V>
__global__ __launch_bounds__(256, 2)
void gemm_tc(const uint16_t* __restrict__ Ahi, const uint16_t* __restrict__ Alo,
             const uint16_t* __restrict__ Bhi, const uint16_t* __restrict__ Blo,
             int K, int N, void* __restrict__ C0v, void* __restrict__ C1v,
             const float* __restrict__ bias, int mode,
             size_t strB, size_t strBias, size_t strC)
{
    constexpr int KPWv  = (V == 0) ? 20 : 36;        // padded row stride (words)
    constexpr int BKv   = (V == 0) ? 32 : 64;        // 16-bit elems per chunk
    constexpr int NKS   = BKv / 16;                  // k16 steps per chunk
    constexpr int MATW  = 128 * KPWv;
    constexpr int STW   = ((V == 0) ? 4 : 2) * MATW;

    extern __shared__ float sm[];
    const int tid  = threadIdx.x;
    const int wid  = tid >> 5, lane = tid & 31;
    const int gid  = lane >> 2, tig = lane & 3;
    const int wm   = wid & 3, wn = wid >> 2;

    const int z = blockIdx.z;
    Bhi += (size_t)z * strB;
    if (V == 0) Blo += (size_t)z * strB;
    if (bias) bias += (size_t)z * strBias;
    const size_t zC = (size_t)z * strC;

    const int mt_n = NTOK / BM, nt_n = N / BN;
    int tile = blockIdx.x;
    int npg  = 8 * nt_n;
    int grp  = tile / npg;
    int fm   = grp * 8;
    int gsz  = min(mt_n - fm, 8);
    int m_t  = fm + (tile % npg) % gsz;
    int n_t  = (tile % npg) / gsz;
    const int row0 = m_t * BM, col0 = n_t * BN;

    const uint32_t smb = smem_u32(sm);
    const int NC = K / BKv;
    const uint32_t bBase = ((V == 0) ? 2u : 1u) * (uint32_t)MATW * 4u;

    const uint32_t laneA_off = (uint32_t)((wm * 32 + (lane & 15)) * KPWv) * 4u
                             + ((lane >> 4) ? 16u : 0u);
    const uint32_t laneB_off = (uint32_t)((wn * 64 + (lane & 7) + ((lane & 16) ? 8 : 0)) * KPWv) * 4u
                             + (((lane >> 3) & 1) ? 16u : 0u);

    auto load_chunk = [&](int c, int s) {
        const int k0 = c * BKv;
        const uint32_t sbase = smb + (uint32_t)(s * STW) * 4u;
        if (V == 0) {
            // 4 matrices x 128 rows x 4 cp16 (64B rows) = 2048 -> 8 iters
#pragma unroll
            for (int i = 0; i < 8; ++i) {
                int id  = i * 256 + tid;
                int mat = id >> 9;
                const uint16_t* src = (mat == 0) ? Ahi : (mat == 1) ? Alo
                                    : (mat == 2) ? Bhi : Blo;
                int base = (mat <= 1) ? row0 : col0;
                int r  = (id >> 2) & 127;
                int c4 = id & 3;
                uint32_t dst = sbase + (uint32_t)(mat * MATW + r * KPWv) * 4u
                             + (uint32_t)c4 * 16u;
                cp16(dst, src + (size_t)(base + r) * K + k0 + c4 * 8);
            }
        } else {
            // 2 matrices x 128 rows x 8 cp16 (128B rows) = 2048 -> 8 iters
#pragma unroll
            for (int i = 0; i < 8; ++i) {
                int id  = i * 256 + tid;
                int mat = id >> 10;               // 0: A, 1: B
                const uint16_t* src = mat ? Bhi : Ahi;
                int base = mat ? col0 : row0;
                int r  = (id >> 3) & 127;
                int c4 = id & 7;
                uint32_t dst = sbase + (uint32_t)(mat * MATW + r * KPWv) * 4u
                             + (uint32_t)c4 * 16u;
                cp16(dst, src + (size_t)(base + r) * K + k0 + c4 * 8);
            }
        }
    };

    float acc[2][8][4];
#pragma unroll
    for (int mt = 0; mt < 2; ++mt)
#pragma unroll
        for (int nt = 0; nt < 8; ++nt)
#pragma unroll
            for (int q = 0; q < 4; ++q) acc[mt][nt][q] = 0.f;

    load_chunk(0, 0); cp_commit();
    if (NC > 1) load_chunk(1, 1);
    cp_commit();

#pragma unroll 1
    for (int c = 0; c < NC; ++c) {
        const int s = c & 1;
        cp_wait1();
        __syncthreads();

        const uint32_t stage = smb + (uint32_t)(s * STW) * 4u;
        const uint32_t aAh = stage + laneA_off;
        const uint32_t aAl = aAh + (uint32_t)MATW * 4u;
        const uint32_t aBh = stage + bBase + laneB_off;
        const uint32_t aBl = aBh + (uint32_t)MATW * 4u;

#pragma unroll
        for (int ks = 0; ks < NKS; ++ks) {
            const uint32_t ko = (uint32_t)ks * 32u;
            uint32_t ah[2][4], al[2][4];
#pragma unroll
            for (int mt = 0; mt < 2; ++mt) {
                ldsm4(ah[mt][0], ah[mt][1], ah[mt][2], ah[mt][3],
                      aAh + (uint32_t)(mt * 16 * KPWv) * 4u + ko);
                if (V == 0)
                    ldsm4(al[mt][0], al[mt][1], al[mt][2], al[mt][3],
                          aAl + (uint32_t)(mt * 16 * KPWv) * 4u + ko);
            }
#pragma unroll
            for (int p = 0; p < 4; ++p) {
                uint32_t bh0, bh1, bh2, bh3;
                ldsm4(bh0, bh1, bh2, bh3, aBh + (uint32_t)(p * 16 * KPWv) * 4u + ko);
                if (V == 0) {
                    uint32_t bl0, bl1, bl2, bl3;
                    ldsm4(bl0, bl1, bl2, bl3, aBl + (uint32_t)(p * 16 * KPWv) * 4u + ko);
#pragma unroll
                    for (int mt = 0; mt < 2; ++mt) {
                        float* ae = acc[mt][2 * p];
                        float* ao = acc[mt][2 * p + 1];
                        mma_bf(ae[0], ae[1], ae[2], ae[3],
                               ah[mt][0], ah[mt][1], ah[mt][2], ah[mt][3], bh0, bh1);
                        mma_bf(ao[0], ao[1], ao[2], ao[3],
                               ah[mt][0], ah[mt][1], ah[mt][2], ah[mt][3], bh2, bh3);
                        mma_bf(ae[0], ae[1], ae[2], ae[3],
                               ah[mt][0], ah[mt][1], ah[mt][2], ah[mt][3], bl0, bl1);
                        mma_bf(ao[0], ao[1], ao[2], ao[3],
                               ah[mt][0], ah[mt][1], ah[mt][2], ah[mt][3], bl2, bl3);
                        mma_bf(ae[0], ae[1], ae[2], ae[3],
                               al[mt][0], al[mt][1], al[mt][2], al[mt][3], bh0, bh1);
                        mma_bf(ao[0], ao[1], ao[2], ao[3],
                               al[mt][0], al[mt][1], al[mt][2], al[mt][3], bh2, bh3);
                    }
                } else {
#pragma unroll
                    for (int mt = 0; mt < 2; ++mt) {
                        float* ae = acc[mt][2 * p];
                        float* ao = acc[mt][2 * p + 1];
                        mma_fp(ae[0], ae[1], ae[2], ae[3],
                               ah[mt][0], ah[mt][1], ah[mt][2], ah[mt][3], bh0, bh1);
                        mma_fp(ao[0], ao[1], ao[2], ao[3],
                               ah[mt][0], ah[mt][1], ah[mt][2], ah[mt][3], bh2, bh3);
                    }
                }
            }
        }
        __syncthreads();
        if (c + 2 < NC) load_chunk(c + 2, s);
        cp_commit();
    }

    // ---- epilogue ----
#pragma unroll
    for (int mt = 0; mt < 2; ++mt) {
#pragma unroll
        for (int nt = 0; nt < 8; ++nt) {
            int row = row0 + wm * 32 + mt * 16 + gid;
            int col = col0 + wn * 64 + nt * 8 + tig * 2;
            float v0 = acc[mt][nt][0], v1 = acc[mt][nt][1];
            float v2 = acc[mt][nt][2], v3 = acc[mt][nt][3];
            if (mode == 2 || mode == 3 || mode == 5) {
                float b0 = bias[col], b1 = bias[col + 1];
                v0 += b0; v1 += b1; v2 += b0; v3 += b1;
            }
            size_t ad0 = (size_t)row * N + col;
            size_t ad1 = (size_t)(row + 8) * N + col;
            if (mode == 2) {
                bf16* o0 = (bf16*)C0v + zC;
                bf16* o1 = (bf16*)C1v + zC;
                bf16 h0 = __float2bfloat16(v0), h1 = __float2bfloat16(v1);
                bf16 h2 = __float2bfloat16(v2), h3 = __float2bfloat16(v3);
                __nv_bfloat162 hh0 = { h0, h1 }, hh1 = { h2, h3 };
                __nv_bfloat162 ll0 = { __float2bfloat16(v0 - __bfloat162float(h0)),
                                       __float2bfloat16(v1 - __bfloat162float(h1)) };
                __nv_bfloat162 ll1 = { __float2bfloat16(v2 - __bfloat162float(h2)),
                                       __float2bfloat16(v3 - __bfloat162float(h3)) };
                *(__nv_bfloat162*)(o0 + ad0) = hh0;  *(__nv_bfloat162*)(o0 + ad1) = hh1;
                *(__nv_bfloat162*)(o1 + ad0) = ll0;  *(__nv_bfloat162*)(o1 + ad1) = ll1;
            } else if (mode == 4 || mode == 5) {
                fp16* o = (fp16*)C0v + zC;
                __half2 q0 = { __float2half(v0), __float2half(v1) };
                __half2 q1 = { __float2half(v2), __float2half(v3) };
                *(__half2*)(o + ad0) = q0;  *(__half2*)(o + ad1) = q1;
            } else {
                float* o = (float*)C0v + zC;
                float2 q0 = { v0, v1 }, q1 = { v2, v3 };
                *(float2*)(o + ad0) = q0;  *(float2*)(o + ad1) = q1;
            }
        }
    }
}

// ---------------- prep / softmax / reduce -----------------------------------
__global__ void split_transpose_x(const float* __restrict__ x, bf16* __restrict__ xhi,
                                  bf16* __restrict__ xlo, fp16* __restrict__ xTh)
{
    __shared__ float t[32][33];
    int c0 = blockIdx.x * 32, r0 = blockIdx.y * 32;
    int tx = threadIdx.x, ty = threadIdx.y;
#pragma unroll
    for (int i = 0; i < 4; ++i) {
        size_t ad = (size_t)(r0 + ty + i*8) * CD + c0 + tx;
        float v = x[ad];
        t[ty + i*8][tx] = v;
        bf16 h = __float2bfloat16(v);
        xhi[ad] = h;
        xlo[ad] = __float2bfloat16(v - __bfloat162float(h));
    }
    __syncthreads();
#pragma unroll
    for (int i = 0; i < 4; ++i) {
        size_t ad = (size_t)(c0 + ty + i*8) * NTOK + r0 + tx;
        xTh[ad] = __float2half(t[tx][ty + i*8]);
    }
}
__global__ void transpose_split_bf2(const float* __restrict__ W0, const float* __restrict__ W1,
                                    bf16* __restrict__ h0, bf16* __restrict__ l0,
                                    bf16* __restrict__ h1, bf16* __restrict__ l1)
{
    __shared__ float t[32][33];
    const float* s = blockIdx.z ? W1 : W0;
    bf16* oh = blockIdx.z ? h1 : h0;
    bf16* ol = blockIdx.z ? l1 : l0;
    int c0 = blockIdx.x * 32, r0 = blockIdx.y * 32;
    int tx = threadIdx.x, ty = threadIdx.y;
#pragma unroll
    for (int i = 0; i < 4; ++i)
        t[ty + i*8][tx] = s[(size_t)(r0 + ty + i*8) * CD + c0 + tx];
    __syncthreads();
#pragma unroll
    for (int i = 0; i < 4; ++i) {
        float v = t[tx][ty + i*8];
        bf16 h = __float2bfloat16(v);
        size_t ad = (size_t)(c0 + ty + i*8) * CD + r0 + tx;
        oh[ad] = h;
        ol[ad] = __float2bfloat16(v - __bfloat162float(h));
    }
}
__global__ void transpose_fp16(const float* __restrict__ src, fp16* __restrict__ dst,
                               int R, int C)
{
    __shared__ float t[32][33];
    const size_t bo = (size_t)blockIdx.z * R * C;
    const float* s = src + bo;
    fp16* o = dst + bo;
    int c0 = blockIdx.x * 32, r0 = blockIdx.y * 32;
    int tx = threadIdx.x, ty = threadIdx.y;
#pragma unroll
    for (int i = 0; i < 4; ++i)
        t[ty + i*8][tx] = s[(size_t)(r0 + ty + i*8) * C + c0 + tx];
    __syncthreads();
#pragma unroll
    for (int i = 0; i < 4; ++i) {
        size_t ad = (size_t)(c0 + ty + i*8) * R + r0 + tx;
        o[ad] = __float2half(t[tx][ty + i*8]);
    }
}
__device__ __forceinline__ float wmax(float v) {
#pragma unroll
    for (int o = 16; o > 0; o >>= 1) v = fmaxf(v, __shfl_xor_sync(0xffffffffu, v, o));
    return v;
}
__device__ __forceinline__ float wsum(float v) {
#pragma unroll
    for (int o = 16; o > 0; o >>= 1) v += __shfl_xor_sync(0xffffffffu, v, o);
    return v;
}
__global__ __launch_bounds__(256, 4)
void softmax_fp16(const float* __restrict__ S, fp16* __restrict__ Phi)
{
    const float* r = S + (size_t)blockIdx.x * NTOK;
    fp16* ph = Phi + (size_t)blockIdx.x * NTOK;
    const int tid = threadIdx.x;
    __shared__ float red[8];
    float v[32];
    float m = -3.4e38f;
#pragma unroll
    for (int i = 0; i < 32; ++i) { v[i] = r[i*256 + tid]; m = fmaxf(m, v[i]); }
    m = wmax(m);
    if ((tid & 31) == 0) red[tid >> 5] = m;
    __syncthreads();
    { float t = red[tid & 7];
      t = fmaxf(t, __shfl_xor_sync(0xffffffffu, t, 1));
      t = fmaxf(t, __shfl_xor_sync(0xffffffffu, t, 2));
      t = fmaxf(t, __shfl_xor_sync(0xffffffffu, t, 4)); m = t; }
    float s = 0.f;
#pragma unroll
    for (int i = 0; i < 32; ++i) { v[i] = __expf(v[i] - m); s += v[i]; }
    s = wsum(s);
    __syncthreads();
    if ((tid & 31) == 0) red[tid >> 5] = s;
    __syncthreads();
    { float t = red[tid & 7];
      t += __shfl_xor_sync(0xffffffffu, t, 1);
      t += __shfl_xor_sync(0xffffffffu, t, 2);
      t += __shfl_xor_sync(0xffffffffu, t, 4); s = t; }
    const float inv = 1.f / s;
#pragma unroll
    for (int i = 0; i < 32; ++i)
        ph[i*256 + tid] = __float2half(v[i] * inv);
}
__global__ void reduce_heads(const fp16* __restrict__ Z, float* __restrict__ out)
{
    const size_t n = (size_t)NTOK * CD / 4;
    const size_t str = n;
    const uint2* z = (const uint2*)Z;
    for (size_t i = (size_t)blockIdx.x * blockDim.x + threadIdx.x; i < n;
         i += (size_t)gridDim.x * blockDim.x) {
        float4 a = { 0.f, 0.f, 0.f, 0.f };
#pragma unroll
        for (int h = 0; h < NH; ++h) {
            uint2 u = z[h * str + i];
            float2 p0 = __half22float2(*(const __half2*)&u.x);
            float2 p1 = __half22float2(*(const __half2*)&u.y);
            a.x += fmaxf(p0.x, 0.f); a.y += fmaxf(p0.y, 0.f);
            a.z += fmaxf(p1.x, 0.f); a.w += fmaxf(p1.y, 0.f);
        }
        a.x *= 0.125f; a.y *= 0.125f; a.z *= 0.125f; a.w *= 0.125f;
        ((float4*)out)[i] = a;
    }
}

// ---------------- host -------------------------------------------------------
extern "C" void kernel_launch(void* const* d_in, const int* in_sizes, int n_in,
                              void* d_out, int out_size)
{
    (void)in_sizes; (void)n_in; (void)out_size;
    const float* x  = (const float*)d_in[0];
    const float* Wt = (const float*)d_in[1];
    const float* bt = (const float*)d_in[2];
    const float* Wp = (const float*)d_in[3];
    const float* bp = (const float*)d_in[4];
    const float* Wk = (const float*)d_in[5];
    const float* bk = (const float*)d_in[6];
    float* out = (float*)d_out;

    bf16 *xhi,*xlo,*WtThi,*WtTlo,*WpThi,*WpTlo,*Qhi,*Qlo,*Khi,*Klo;
    fp16 *xTh,*WkTh,*Phi,*Yh,*Z;
    float *S;
    cudaGetSymbolAddress((void**)&xhi, g_xhi);   cudaGetSymbolAddress((void**)&xlo, g_xlo);
    cudaGetSymbolAddress((void**)&WtThi, g_WtThi); cudaGetSymbolAddress((void**)&WtTlo, g_WtTlo);
    cudaGetSymbolAddress((void**)&WpThi, g_WpThi); cudaGetSymbolAddress((void**)&WpTlo, g_WpTlo);
    cudaGetSymbolAddress((void**)&Qhi, g_Qhi);   cudaGetSymbolAddress((void**)&Qlo, g_Qlo);
    cudaGetSymbolAddress((void**)&Khi, g_Khi);   cudaGetSymbolAddress((void**)&Klo, g_Klo);
    cudaGetSymbolAddress((void**)&xTh, g_xTh);   cudaGetSymbolAddress((void**)&WkTh, g_WkTh);
    cudaGetSymbolAddress((void**)&Phi, g_Phi);   cudaGetSymbolAddress((void**)&Yh, g_Yh);
    cudaGetSymbolAddress((void**)&S, g_S);       cudaGetSymbolAddress((void**)&Z, g_Z);

    cudaFuncSetAttribute(gemm_tc<0>, cudaFuncAttributeMaxDynamicSharedMemorySize, SMEM_V0);
    cudaFuncSetAttribute(gemm_tc<2>, cudaFuncAttributeMaxDynamicSharedMemorySize, SMEM_V2);

    // prep (3 launches)
    split_transpose_x<<<dim3(CD/32, NTOK/32), dim3(32, 8)>>>(x, xhi, xlo, xTh);
    transpose_split_bf2<<<dim3(CD/32, CD/32, 2), dim3(32, 8)>>>(
        Wt, Wp, WtThi, WtTlo, WpThi, WpTlo);
    transpose_fp16<<<dim3(CD/32, CD/32, NH), dim3(32, 8)>>>(Wk, WkTh, CD, CD);

    const int mt = NTOK / BM;            // 64
    // Q/K projections (bf16x3, split bf16 out)
    gemm_tc<0><<<mt * (CD/BN), 256, SMEM_V0>>>(
        (const uint16_t*)xhi, (const uint16_t*)xlo,
        (const uint16_t*)WtThi, (const uint16_t*)WtTlo,
        CD, CD, Qhi, Qlo, bt, 2, 0, 0, 0);
    gemm_tc<0><<<mt * (CD/BN), 256, SMEM_V0>>>(
        (const uint16_t*)xhi, (const uint16_t*)xlo,
        (const uint16_t*)WpThi, (const uint16_t*)WpTlo,
        CD, CD, Khi, Klo, bp, 2, 0, 0, 0);
    // sim (bf16x3, fp32 out)
    gemm_tc<0><<<mt * (NTOK/BN), 256, SMEM_V0>>>(
        (const uint16_t*)Qhi, (const uint16_t*)Qlo,
        (const uint16_t*)Khi, (const uint16_t*)Klo,
        CD, NTOK, S, nullptr, nullptr, 0, 0, 0, 0);
    // softmax -> fp16 P
    softmax_fp16<<<NTOK, 256>>>(S, Phi);
    // Y = P @ x (fp16 single pass, BK=64, fp16 out)
    gemm_tc<2><<<mt * (CD/BN), 256, SMEM_V2>>>(
        (const uint16_t*)Phi, nullptr,
        (const uint16_t*)xTh, nullptr,
        NTOK, CD, Yh, nullptr, nullptr, 4, 0, 0, 0);
    // Z[h] = Y @ Wk[h]^T + bk[h] (fp16 single pass, BK=64, fp16 out)
    gemm_tc<2><<<dim3(mt * (CD/BN), 1, NH), 256, SMEM_V2>>>(
        (const uint16_t*)Yh, nullptr,
        (const uint16_t*)WkTh, nullptr,
        CD, CD, Z, nullptr, bk, 5,
        (size_t)CD * CD, (size_t)CD, (size_t)NTOK * CD);
    // out = mean_h relu(Z)
    reduce_heads<<<512, 256>>>(Z, out);
}

// round 15
// speedup vs baseline: 1.1073x; 1.0033x over previous
#include <cuda_runtime.h>
#include <cuda_bf16.h>
#include <cuda_fp16.h>
#include <cstdint>
#include <cstddef>

#define NTOK 8192
#define CD   512
#define NH   8

#define BM 128
#define BN 128

typedef __nv_bfloat16 bf16;
typedef __half fp16;

// V0 (bf16x3): BK=32, KPW=20;  V2 (fp16 single): BK=64, KPW=36
#define SMEM_V0 (2 * 4 * (128 * 20) * 4)     // 81920
#define SMEM_V2 (2 * 2 * (128 * 36) * 4)     // 73728

// ---------------- scratch ----------------------------------------------------
__device__ bf16 g_xhi[NTOK*CD],  g_xlo[NTOK*CD];
__device__ bf16 g_WThi[2*CD*CD], g_WTlo[2*CD*CD];     // Wt^T, Wp^T paired
__device__ bf16 g_QKhi[2*NTOK*CD], g_QKlo[2*NTOK*CD]; // Q, K paired
__device__ float g_bias2[2*CD];                        // bt, bp contiguous
__device__ fp16 g_xTh[CD*NTOK];
__device__ fp16 g_WkTh[NH*CD*CD];
__device__ fp16 g_Phi[(size_t)NTOK*NTOK];
__device__ fp16 g_Yh[NTOK*CD];
__device__ float g_S[(size_t)NTOK*NTOK];
__device__ fp16 g_Z[(size_t)NH*NTOK*CD];

// ---------------- helpers ----------------------------------------------------
__device__ __forceinline__ uint32_t smem_u32(const void* p) {
    uint32_t a;
    asm("{ .reg .u64 t; cvta.to.shared.u64 t, %1; cvt.u32.u64 %0, t; }" : "=r"(a) : "l"(p));
    return a;
}
__device__ __forceinline__ void cp16(uint32_t d, const void* s) {
    asm volatile("cp.async.cg.shared.global [%0], [%1], 16;" :: "r"(d), "l"(s));
}
__device__ __forceinline__ void cp_commit() { asm volatile("cp.async.commit_group;"); }
__device__ __forceinline__ void cp_wait1()  { asm volatile("cp.async.wait_group 1;"); }

__device__ __forceinline__ void ldsm4(uint32_t& r0, uint32_t& r1, uint32_t& r2, uint32_t& r3,
                                      uint32_t addr) {
    asm volatile("ldmatrix.sync.aligned.m8n8.x4.shared.b16 {%0,%1,%2,%3}, [%4];"
                 : "=r"(r0), "=r"(r1), "=r"(r2), "=r"(r3) : "r"(addr));
}
__device__ __forceinline__ void mma_bf(float& c0, float& c1, float& c2, float& c3,
                                       uint32_t a0, uint32_t a1, uint32_t a2, uint32_t a3,
                                       uint32_t b0, uint32_t b1) {
    asm volatile(
        "mma.sync.aligned.m16n8k16.row.col.f32.bf16.bf16.f32 "
        "{%0,%1,%2,%3}, {%4,%5,%6,%7}, {%8,%9}, {%0,%1,%2,%3};"
        : "+f"(c0), "+f"(c1), "+f"(c2), "+f"(c3)
        : "r"(a0), "r"(a1), "r"(a2), "r"(a3), "r"(b0), "r"(b1));
}
__device__ __forceinline__ void mma_fp(float& c0, float& c1, float& c2, float& c3,
                                       uint32_t a0, uint32_t a1, uint32_t a2, uint32_t a3,
                                       uint32_t b0, uint32_t b1) {
    asm volatile(
        "mma.sync.aligned.m16n8k16.row.col.f32.f16.f16.f32 "
        "{%0,%1,%2,%3}, {%4,%5,%6,%7}, {%8,%9}, {%0,%1,%2,%3};"
        : "+f"(c0), "+f"(c1), "+f"(c2), "+f"(c3)
        : "r"(a0), "r"(a1), "r"(a2), "r"(a3), "r"(b0), "r"(b1));
}

// ---------------- tensor GEMM: C[8192, N] = A @ B^T -------------------------
// V=0: bf16x3 (A hi/lo mats 0/1, B hi/lo mats 2/3), BK=32, KPW=20
// V=2: fp16 single-pass (A mat 0, B mat 1), BK=64, KPW=36
// mode 0: fp32->C0  2: +bias split bf16->C0/C1  3: +bias fp32->C0
// mode 4: fp16->C0  5: +bias fp16->C0
template<int V>
__global__ __launch_bounds__(256, 2)
void gemm_tc(const uint16_t* __restrict__ Ahi, const uint16_t* __restrict__ Alo,
             const uint16_t* __restrict__ Bhi, const uint16_t* __restrict__ Blo,
             int K, int N, void* __restrict__ C0v, void* __restrict__ C1v,
             const float* __restrict__ bias, int mode,
             size_t strB, size_t strBias, size_t strC)
{
    constexpr int KPWv  = (V == 0) ? 20 : 36;
    constexpr int BKv   = (V == 0) ? 32 : 64;
    constexpr int NKS   = BKv / 16;
    constexpr int MATW  = 128 * KPWv;
    constexpr int STW   = ((V == 0) ? 4 : 2) * MATW;

    extern __shared__ float sm[];
    const int tid  = threadIdx.x;
    const int wid  = tid >> 5, lane = tid & 31;
    const int gid  = lane >> 2, tig = lane & 3;
    const int wm   = wid & 3, wn = wid >> 2;

    const int z = blockIdx.z;
    Bhi += (size_t)z * strB;
    if (V == 0) Blo += (size_t)z * strB;
    if (bias) bias += (size_t)z * strBias;
    const size_t zC = (size_t)z * strC;

    const int mt_n = NTOK / BM, nt_n = N / BN;
    int tile = blockIdx.x;
    int npg  = 8 * nt_n;
    int grp  = tile / npg;
    int fm   = grp * 8;
    int gsz  = min(mt_n - fm, 8);
    int m_t  = fm + (tile % npg) % gsz;
    int n_t  = (tile % npg) / gsz;
    const int row0 = m_t * BM, col0 = n_t * BN;

    const uint32_t smb = smem_u32(sm);
    const int NC = K / BKv;
    const uint32_t bBase = ((V == 0) ? 2u : 1u) * (uint32_t)MATW * 4u;

    const uint32_t laneA_off = (uint32_t)((wm * 32 + (lane & 15)) * KPWv) * 4u
                             + ((lane >> 4) ? 16u : 0u);
    const uint32_t laneB_off = (uint32_t)((wn * 64 + (lane & 7) + ((lane & 16) ? 8 : 0)) * KPWv) * 4u
                             + (((lane >> 3) & 1) ? 16u : 0u);

    auto load_chunk = [&](int c, int s) {
        const int k0 = c * BKv;
        const uint32_t sbase = smb + (uint32_t)(s * STW) * 4u;
        if (V == 0) {
#pragma unroll
            for (int i = 0; i < 8; ++i) {
                int id  = i * 256 + tid;
                int mat = id >> 9;
                const uint16_t* src = (mat == 0) ? Ahi : (mat == 1) ? Alo
                                    : (mat == 2) ? Bhi : Blo;
                int base = (mat <= 1) ? row0 : col0;
                int r  = (id >> 2) & 127;
                int c4 = id & 3;
                uint32_t dst = sbase + (uint32_t)(mat * MATW + r * KPWv) * 4u
                             + (uint32_t)c4 * 16u;
                cp16(dst, src + (size_t)(base + r) * K + k0 + c4 * 8);
            }
        } else {
#pragma unroll
            for (int i = 0; i < 8; ++i) {
                int id  = i * 256 + tid;
                int mat = id >> 10;
                const uint16_t* src = mat ? Bhi : Ahi;
                int base = mat ? col0 : row0;
                int r  = (id >> 3) & 127;
                int c4 = id & 7;
                uint32_t dst = sbase + (uint32_t)(mat * MATW + r * KPWv) * 4u
                             + (uint32_t)c4 * 16u;
                cp16(dst, src + (size_t)(base + r) * K + k0 + c4 * 8);
            }
        }
    };

    float acc[2][8][4];
#pragma unroll
    for (int mt = 0; mt < 2; ++mt)
#pragma unroll
        for (int nt = 0; nt < 8; ++nt)
#pragma unroll
            for (int q = 0; q < 4; ++q) acc[mt][nt][q] = 0.f;

    load_chunk(0, 0); cp_commit();
    if (NC > 1) load_chunk(1, 1);
    cp_commit();

#pragma unroll 1
    for (int c = 0; c < NC; ++c) {
        const int s = c & 1;
        cp_wait1();
        __syncthreads();

        const uint32_t stage = smb + (uint32_t)(s * STW) * 4u;
        const uint32_t aAh = stage + laneA_off;
        const uint32_t aAl = aAh + (uint32_t)MATW * 4u;
        const uint32_t aBh = stage + bBase + laneB_off;
        const uint32_t aBl = aBh + (uint32_t)MATW * 4u;

#pragma unroll
        for (int ks = 0; ks < NKS; ++ks) {
            const uint32_t ko = (uint32_t)ks * 32u;
            uint32_t ah[2][4], al[2][4];
#pragma unroll
            for (int mt = 0; mt < 2; ++mt) {
                ldsm4(ah[mt][0], ah[mt][1], ah[mt][2], ah[mt][3],
                      aAh + (uint32_t)(mt * 16 * KPWv) * 4u + ko);
                if (V == 0)
                    ldsm4(al[mt][0], al[mt][1], al[mt][2], al[mt][3],
                          aAl + (uint32_t)(mt * 16 * KPWv) * 4u + ko);
            }
#pragma unroll
            for (int p = 0; p < 4; ++p) {
                uint32_t bh0, bh1, bh2, bh3;
                ldsm4(bh0, bh1, bh2, bh3, aBh + (uint32_t)(p * 16 * KPWv) * 4u + ko);
                if (V == 0) {
                    uint32_t bl0, bl1, bl2, bl3;
                    ldsm4(bl0, bl1, bl2, bl3, aBl + (uint32_t)(p * 16 * KPWv) * 4u + ko);
#pragma unroll
                    for (int mt = 0; mt < 2; ++mt) {
                        float* ae = acc[mt][2 * p];
                        float* ao = acc[mt][2 * p + 1];
                        mma_bf(ae[0], ae[1], ae[2], ae[3],
                               ah[mt][0], ah[mt][1], ah[mt][2], ah[mt][3], bh0, bh1);
                        mma_bf(ao[0], ao[1], ao[2], ao[3],
                               ah[mt][0], ah[mt][1], ah[mt][2], ah[mt][3], bh2, bh3);
                        mma_bf(ae[0], ae[1], ae[2], ae[3],
                               ah[mt][0], ah[mt][1], ah[mt][2], ah[mt][3], bl0, bl1);
                        mma_bf(ao[0], ao[1], ao[2], ao[3],
                               ah[mt][0], ah[mt][1], ah[mt][2], ah[mt][3], bl2, bl3);
                        mma_bf(ae[0], ae[1], ae[2], ae[3],
                               al[mt][0], al[mt][1], al[mt][2], al[mt][3], bh0, bh1);
                        mma_bf(ao[0], ao[1], ao[2], ao[3],
                               al[mt][0], al[mt][1], al[mt][2], al[mt][3], bh2, bh3);
                    }
                } else {
#pragma unroll
                    for (int mt = 0; mt < 2; ++mt) {
                        float* ae = acc[mt][2 * p];
                        float* ao = acc[mt][2 * p + 1];
                        mma_fp(ae[0], ae[1], ae[2], ae[3],
                               ah[mt][0], ah[mt][1], ah[mt][2], ah[mt][3], bh0, bh1);
                        mma_fp(ao[0], ao[1], ao[2], ao[3],
                               ah[mt][0], ah[mt][1], ah[mt][2], ah[mt][3], bh2, bh3);
                    }
                }
            }
        }
        __syncthreads();
        if (c + 2 < NC) load_chunk(c + 2, s);
        cp_commit();
    }

    // ---- epilogue ----
#pragma unroll
    for (int mt = 0; mt < 2; ++mt) {
#pragma unroll
        for (int nt = 0; nt < 8; ++nt) {
            int row = row0 + wm * 32 + mt * 16 + gid;
            int col = col0 + wn * 64 + nt * 8 + tig * 2;
            float v0 = acc[mt][nt][0], v1 = acc[mt][nt][1];
            float v2 = acc[mt][nt][2], v3 = acc[mt][nt][3];
            if (mode == 2 || mode == 3 || mode == 5) {
                float b0 = bias[col], b1 = bias[col + 1];
                v0 += b0; v1 += b1; v2 += b0; v3 += b1;
            }
            size_t ad0 = (size_t)row * N + col;
            size_t ad1 = (size_t)(row + 8) * N + col;
            if (mode == 2) {
                bf16* o0 = (bf16*)C0v + zC;
                bf16* o1 = (bf16*)C1v + zC;
                bf16 h0 = __float2bfloat16(v0), h1 = __float2bfloat16(v1);
                bf16 h2 = __float2bfloat16(v2), h3 = __float2bfloat16(v3);
                __nv_bfloat162 hh0 = { h0, h1 }, hh1 = { h2, h3 };
                __nv_bfloat162 ll0 = { __float2bfloat16(v0 - __bfloat162float(h0)),
                                       __float2bfloat16(v1 - __bfloat162float(h1)) };
                __nv_bfloat162 ll1 = { __float2bfloat16(v2 - __bfloat162float(h2)),
                                       __float2bfloat16(v3 - __bfloat162float(h3)) };
                *(__nv_bfloat162*)(o0 + ad0) = hh0;  *(__nv_bfloat162*)(o0 + ad1) = hh1;
                *(__nv_bfloat162*)(o1 + ad0) = ll0;  *(__nv_bfloat162*)(o1 + ad1) = ll1;
            } else if (mode == 4 || mode == 5) {
                fp16* o = (fp16*)C0v + zC;
                __half2 q0 = { __float2half(v0), __float2half(v1) };
                __half2 q1 = { __float2half(v2), __float2half(v3) };
                *(__half2*)(o + ad0) = q0;  *(__half2*)(o + ad1) = q1;
            } else {
                float* o = (float*)C0v + zC;
                float2 q0 = { v0, v1 }, q1 = { v2, v3 };
                *(float2*)(o + ad0) = q0;  *(float2*)(o + ad1) = q1;
            }
        }
    }
}

// ---------------- prep / softmax / reduce -----------------------------------
__global__ void copy_bias2(const float* __restrict__ b0, const float* __restrict__ b1,
                           float* __restrict__ dst)
{
    int i = threadIdx.x;
    dst[i] = b0[i];
    dst[CD + i] = b1[i];
}
__global__ void split_transpose_x(const float* __restrict__ x, bf16* __restrict__ xhi,
                                  bf16* __restrict__ xlo, fp16* __restrict__ xTh)
{
    __shared__ float t[32][33];
    int c0 = blockIdx.x * 32, r0 = blockIdx.y * 32;
    int tx = threadIdx.x, ty = threadIdx.y;
#pragma unroll
    for (int i = 0; i < 4; ++i) {
        size_t ad = (size_t)(r0 + ty + i*8) * CD + c0 + tx;
        float v = x[ad];
        t[ty + i*8][tx] = v;
        bf16 h = __float2bfloat16(v);
        xhi[ad] = h;
        xlo[ad] = __float2bfloat16(v - __bfloat162float(h));
    }
    __syncthreads();
#pragma unroll
    for (int i = 0; i < 4; ++i) {
        size_t ad = (size_t)(c0 + ty + i*8) * NTOK + r0 + tx;
        xTh[ad] = __float2half(t[tx][ty + i*8]);
    }
}
// Wt and Wp transpose+split into paired arrays (z selects)
__global__ void transpose_split_bf2(const float* __restrict__ W0, const float* __restrict__ W1,
                                    bf16* __restrict__ dhi, bf16* __restrict__ dlo)
{
    __shared__ float t[32][33];
    const float* s = blockIdx.z ? W1 : W0;
    bf16* oh = dhi + (size_t)blockIdx.z * CD * CD;
    bf16* ol = dlo + (size_t)blockIdx.z * CD * CD;
    int c0 = blockIdx.x * 32, r0 = blockIdx.y * 32;
    int tx = threadIdx.x, ty = threadIdx.y;
#pragma unroll
    for (int i = 0; i < 4; ++i)
        t[ty + i*8][tx] = s[(size_t)(r0 + ty + i*8) * CD + c0 + tx];
    __syncthreads();
#pragma unroll
    for (int i = 0; i < 4; ++i) {
        float v = t[tx][ty + i*8];
        bf16 h = __float2bfloat16(v);
        size_t ad = (size_t)(c0 + ty + i*8) * CD + r0 + tx;
        oh[ad] = h;
        ol[ad] = __float2bfloat16(v - __bfloat162float(h));
    }
}
__global__ void transpose_fp16(const float* __restrict__ src, fp16* __restrict__ dst,
                               int R, int C)
{
    __shared__ float t[32][33];
    const size_t bo = (size_t)blockIdx.z * R * C;
    const float* s = src + bo;
    fp16* o = dst + bo;
    int c0 = blockIdx.x * 32, r0 = blockIdx.y * 32;
    int tx = threadIdx.x, ty = threadIdx.y;
#pragma unroll
    for (int i = 0; i < 4; ++i)
        t[ty + i*8][tx] = s[(size_t)(r0 + ty + i*8) * C + c0 + tx];
    __syncthreads();
#pragma unroll
    for (int i = 0; i < 4; ++i) {
        size_t ad = (size_t)(c0 + ty + i*8) * R + r0 + tx;
        o[ad] = __float2half(t[tx][ty + i*8]);
    }
}
__device__ __forceinline__ float wmax(float v) {
#pragma unroll
    for (int o = 16; o > 0; o >>= 1) v = fmaxf(v, __shfl_xor_sync(0xffffffffu, v, o));
    return v;
}
__device__ __forceinline__ float wsum(float v) {
#pragma unroll
    for (int o = 16; o > 0; o >>= 1) v += __shfl_xor_sync(0xffffffffu, v, o);
    return v;
}
__global__ __launch_bounds__(256, 4)
void softmax_fp16(const float* __restrict__ S, fp16* __restrict__ Phi)
{
    const float* r = S + (size_t)blockIdx.x * NTOK;
    fp16* ph = Phi + (size_t)blockIdx.x * NTOK;
    const int tid = threadIdx.x;
    __shared__ float red[8];
    float v[32];
    float m = -3.4e38f;
#pragma unroll
    for (int i = 0; i < 32; ++i) { v[i] = r[i*256 + tid]; m = fmaxf(m, v[i]); }
    m = wmax(m);
    if ((tid & 31) == 0) red[tid >> 5] = m;
    __syncthreads();
    { float t = red[tid & 7];
      t = fmaxf(t, __shfl_xor_sync(0xffffffffu, t, 1));
      t = fmaxf(t, __shfl_xor_sync(0xffffffffu, t, 2));
      t = fmaxf(t, __shfl_xor_sync(0xffffffffu, t, 4)); m = t; }
    float s = 0.f;
#pragma unroll
    for (int i = 0; i < 32; ++i) { v[i] = __expf(v[i] - m); s += v[i]; }
    s = wsum(s);
    __syncthreads();
    if ((tid & 31) == 0) red[tid >> 5] = s;
    __syncthreads();
    { float t = red[tid & 7];
      t += __shfl_xor_sync(0xffffffffu, t, 1);
      t += __shfl_xor_sync(0xffffffffu, t, 2);
      t += __shfl_xor_sync(0xffffffffu, t, 4); s = t; }
    const float inv = 1.f / s;
#pragma unroll
    for (int i = 0; i < 32; ++i)
        ph[i*256 + tid] = __float2half(v[i] * inv);
}
__global__ void reduce_heads(const fp16* __restrict__ Z, float* __restrict__ out)
{
    const size_t n = (size_t)NTOK * CD / 4;
    const size_t str = n;
    const uint2* z = (const uint2*)Z;
    for (size_t i = (size_t)blockIdx.x * blockDim.x + threadIdx.x; i < n;
         i += (size_t)gridDim.x * blockDim.x) {
        float4 a = { 0.f, 0.f, 0.f, 0.f };
#pragma unroll
        for (int h = 0; h < NH; ++h) {
            uint2 u = z[h * str + i];
            float2 p0 = __half22float2(*(const __half2*)&u.x);
            float2 p1 = __half22float2(*(const __half2*)&u.y);
            a.x += fmaxf(p0.x, 0.f); a.y += fmaxf(p0.y, 0.f);
            a.z += fmaxf(p1.x, 0.f); a.w += fmaxf(p1.y, 0.f);
        }
        a.x *= 0.125f; a.y *= 0.125f; a.z *= 0.125f; a.w *= 0.125f;
        ((float4*)out)[i] = a;
    }
}

// ---------------- host -------------------------------------------------------
extern "C" void kernel_launch(void* const* d_in, const int* in_sizes, int n_in,
                              void* d_out, int out_size)
{
    (void)in_sizes; (void)n_in; (void)out_size;
    const float* x  = (const float*)d_in[0];
    const float* Wt = (const float*)d_in[1];
    const float* bt = (const float*)d_in[2];
    const float* Wp = (const float*)d_in[3];
    const float* bp = (const float*)d_in[4];
    const float* Wk = (const float*)d_in[5];
    const float* bk = (const float*)d_in[6];
    float* out = (float*)d_out;

    bf16 *xhi,*xlo,*WThi,*WTlo,*QKhi,*QKlo;
    fp16 *xTh,*WkTh,*Phi,*Yh,*Z;
    float *S,*bias2;
    cudaGetSymbolAddress((void**)&xhi, g_xhi);   cudaGetSymbolAddress((void**)&xlo, g_xlo);
    cudaGetSymbolAddress((void**)&WThi, g_WThi); cudaGetSymbolAddress((void**)&WTlo, g_WTlo);
    cudaGetSymbolAddress((void**)&QKhi, g_QKhi); cudaGetSymbolAddress((void**)&QKlo, g_QKlo);
    cudaGetSymbolAddress((void**)&bias2, g_bias2);
    cudaGetSymbolAddress((void**)&xTh, g_xTh);   cudaGetSymbolAddress((void**)&WkTh, g_WkTh);
    cudaGetSymbolAddress((void**)&Phi, g_Phi);   cudaGetSymbolAddress((void**)&Yh, g_Yh);
    cudaGetSymbolAddress((void**)&S, g_S);       cudaGetSymbolAddress((void**)&Z, g_Z);

    cudaFuncSetAttribute(gemm_tc<0>, cudaFuncAttributeMaxDynamicSharedMemorySize, SMEM_V0);
    cudaFuncSetAttribute(gemm_tc<2>, cudaFuncAttributeMaxDynamicSharedMemorySize, SMEM_V2);

    // prep
    copy_bias2<<<1, CD>>>(bt, bp, bias2);
    split_transpose_x<<<dim3(CD/32, NTOK/32), dim3(32, 8)>>>(x, xhi, xlo, xTh);
    transpose_split_bf2<<<dim3(CD/32, CD/32, 2), dim3(32, 8)>>>(Wt, Wp, WThi, WTlo);
    transpose_fp16<<<dim3(CD/32, CD/32, NH), dim3(32, 8)>>>(Wk, WkTh, CD, CD);

    const int mt = NTOK / BM;            // 64
    const size_t QKstr = (size_t)NTOK * CD;
    // Q and K projections fused: z=0 -> Q (Wt, bt), z=1 -> K (Wp, bp)
    gemm_tc<0><<<dim3(mt * (CD/BN), 1, 2), 256, SMEM_V0>>>(
        (const uint16_t*)xhi, (const uint16_t*)xlo,
        (const uint16_t*)WThi, (const uint16_t*)WTlo,
        CD, CD, QKhi, QKlo, bias2, 2,
        (size_t)CD * CD, (size_t)CD, QKstr);
    // sim (bf16x3, fp32 out): A = Q, B = K
    gemm_tc<0><<<mt * (NTOK/BN), 256, SMEM_V0>>>(
        (const uint16_t*)QKhi, (const uint16_t*)QKlo,
        (const uint16_t*)(QKhi + QKstr), (const uint16_t*)(QKlo + QKstr),
        CD, NTOK, S, nullptr, nullptr, 0, 0, 0, 0);
    // softmax -> fp16 P
    softmax_fp16<<<NTOK, 256>>>(S, Phi);
    // Y = P @ x (fp16 single pass, BK=64, fp16 out)
    gemm_tc<2><<<mt * (CD/BN), 256, SMEM_V2>>>(
        (const uint16_t*)Phi, nullptr,
        (const uint16_t*)xTh, nullptr,
        NTOK, CD, Yh, nullptr, nullptr, 4, 0, 0, 0);
    // Z[h] = Y @ Wk[h]^T + bk[h] (fp16 single pass, BK=64, fp16 out)
    gemm_tc<2><<<dim3(mt * (CD/BN), 1, NH), 256, SMEM_V2>>>(
        (const uint16_t*)Yh, nullptr,
        (const uint16_t*)WkTh, nullptr,
        CD, CD, Z, nullptr, bk, 5,
        (size_t)CD * CD, (size_t)CD, (size_t)NTOK * CD);
    // out = mean_h relu(Z)
    reduce_heads<<<512, 256>>>(Z, out);
}

// round 16
// speedup vs baseline: 1.1143x; 1.0063x over previous
#include <cuda_runtime.h>
#include <cuda_bf16.h>
#include <cuda_fp16.h>
#include <cstdint>
#include <cstddef>

#define NTOK 8192
#define CD   512
#define NH   8

#define BM 128
#define BN 128

typedef __nv_bfloat16 bf16;
typedef __half fp16;

// V0 (bf16x3): BK=32, KPW=20, 2 stages;  V2 (fp16 single): BK=64, KPW=36, 3 stages
#define SMEM_V0 (2 * 4 * (128 * 20) * 4)     // 81920
#define SMEM_V2 (3 * 2 * (128 * 36) * 4)     // 110592

// ---------------- scratch ----------------------------------------------------
__device__ bf16 g_xhi[NTOK*CD],  g_xlo[NTOK*CD];
__device__ bf16 g_WThi[2*CD*CD], g_WTlo[2*CD*CD];     // Wt^T, Wp^T paired
__device__ bf16 g_QKhi[2*NTOK*CD], g_QKlo[2*NTOK*CD]; // Q, K paired
__device__ float g_bias2[2*CD];                        // bt, bp contiguous
__device__ fp16 g_xTh[CD*NTOK];
__device__ fp16 g_WkTh[NH*CD*CD];
__device__ fp16 g_Phi[(size_t)NTOK*NTOK];
__device__ fp16 g_Yh[NTOK*CD];
__device__ float g_S[(size_t)NTOK*NTOK];
__device__ fp16 g_Z[(size_t)NH*NTOK*CD];

// ---------------- helpers ----------------------------------------------------
__device__ __forceinline__ uint32_t smem_u32(const void* p) {
    uint32_t a;
    asm("{ .reg .u64 t; cvta.to.shared.u64 t, %1; cvt.u32.u64 %0, t; }" : "=r"(a) : "l"(p));
    return a;
}
__device__ __forceinline__ void cp16(uint32_t d, const void* s) {
    asm volatile("cp.async.cg.shared.global [%0], [%1], 16;" :: "r"(d), "l"(s));
}
__device__ __forceinline__ void cp_commit() { asm volatile("cp.async.commit_group;"); }
__device__ __forceinline__ void cp_wait1()  { asm volatile("cp.async.wait_group 1;"); }

__device__ __forceinline__ void ldsm4(uint32_t& r0, uint32_t& r1, uint32_t& r2, uint32_t& r3,
                                      uint32_t addr) {
    asm volatile("ldmatrix.sync.aligned.m8n8.x4.shared.b16 {%0,%1,%2,%3}, [%4];"
                 : "=r"(r0), "=r"(r1), "=r"(r2), "=r"(r3) : "r"(addr));
}
__device__ __forceinline__ void mma_bf(float& c0, float& c1, float& c2, float& c3,
                                       uint32_t a0, uint32_t a1, uint32_t a2, uint32_t a3,
                                       uint32_t b0, uint32_t b1) {
    asm volatile(
        "mma.sync.aligned.m16n8k16.row.col.f32.bf16.bf16.f32 "
        "{%0,%1,%2,%3}, {%4,%5,%6,%7}, {%8,%9}, {%0,%1,%2,%3};"
        : "+f"(c0), "+f"(c1), "+f"(c2), "+f"(c3)
        : "r"(a0), "r"(a1), "r"(a2), "r"(a3), "r"(b0), "r"(b1));
}
__device__ __forceinline__ void mma_fp(float& c0, float& c1, float& c2, float& c3,
                                       uint32_t a0, uint32_t a1, uint32_t a2, uint32_t a3,
                                       uint32_t b0, uint32_t b1) {
    asm volatile(
        "mma.sync.aligned.m16n8k16.row.col.f32.f16.f16.f32 "
        "{%0,%1,%2,%3}, {%4,%5,%6,%7}, {%8,%9}, {%0,%1,%2,%3};"
        : "+f"(c0), "+f"(c1), "+f"(c2), "+f"(c3)
        : "r"(a0), "r"(a1), "r"(a2), "r"(a3), "r"(b0), "r"(b1));
}

// ---------------- tensor GEMM: C[8192, N] = A @ B^T -------------------------
// V=0: bf16x3 (A hi/lo mats 0/1, B hi/lo mats 2/3), BK=32, KPW=20, 2 stages
// V=2: fp16 single-pass (A mat 0, B mat 1), BK=64, KPW=36, 3 stages
// Both keep the proven schedule: wait -> barrier -> compute -> barrier -> load.
// mode 0: fp32->C0  2: +bias split bf16->C0/C1  3: +bias fp32->C0
// mode 4: fp16->C0  5: +bias fp16->C0
template<int V>
__global__ __launch_bounds__(256, 2)
void gemm_tc(const uint16_t* __restrict__ Ahi, const uint16_t* __restrict__ Alo,
             const uint16_t* __restrict__ Bhi, const uint16_t* __restrict__ Blo,
             int K, int N, void* __restrict__ C0v, void* __restrict__ C1v,
             const float* __restrict__ bias, int mode,
             size_t strB, size_t strBias, size_t strC)
{
    constexpr int KPWv  = (V == 0) ? 20 : 36;
    constexpr int BKv   = (V == 0) ? 32 : 64;
    constexpr int NKS   = BKv / 16;
    constexpr int MATW  = 128 * KPWv;
    constexpr int STW   = ((V == 0) ? 4 : 2) * MATW;
    constexpr int NSTG  = (V == 0) ? 2 : 3;

    extern __shared__ float sm[];
    const int tid  = threadIdx.x;
    const int wid  = tid >> 5, lane = tid & 31;
    const int gid  = lane >> 2, tig = lane & 3;
    const int wm   = wid & 3, wn = wid >> 2;

    const int z = blockIdx.z;
    Bhi += (size_t)z * strB;
    if (V == 0) Blo += (size_t)z * strB;
    if (bias) bias += (size_t)z * strBias;
    const size_t zC = (size_t)z * strC;

    const int mt_n = NTOK / BM, nt_n = N / BN;
    int tile = blockIdx.x;
    int npg  = 8 * nt_n;
    int grp  = tile / npg;
    int fm   = grp * 8;
    int gsz  = min(mt_n - fm, 8);
    int m_t  = fm + (tile % npg) % gsz;
    int n_t  = (tile % npg) / gsz;
    const int row0 = m_t * BM, col0 = n_t * BN;

    const uint32_t smb = smem_u32(sm);
    const int NC = K / BKv;
    const uint32_t bBase = ((V == 0) ? 2u : 1u) * (uint32_t)MATW * 4u;

    const uint32_t laneA_off = (uint32_t)((wm * 32 + (lane & 15)) * KPWv) * 4u
                             + ((lane >> 4) ? 16u : 0u);
    const uint32_t laneB_off = (uint32_t)((wn * 64 + (lane & 7) + ((lane & 16) ? 8 : 0)) * KPWv) * 4u
                             + (((lane >> 3) & 1) ? 16u : 0u);

    auto load_chunk = [&](int c, int s) {
        const int k0 = c * BKv;
        const uint32_t sbase = smb + (uint32_t)(s * STW) * 4u;
        if (V == 0) {
#pragma unroll
            for (int i = 0; i < 8; ++i) {
                int id  = i * 256 + tid;
                int mat = id >> 9;
                const uint16_t* src = (mat == 0) ? Ahi : (mat == 1) ? Alo
                                    : (mat == 2) ? Bhi : Blo;
                int base = (mat <= 1) ? row0 : col0;
                int r  = (id >> 2) & 127;
                int c4 = id & 3;
                uint32_t dst = sbase + (uint32_t)(mat * MATW + r * KPWv) * 4u
                             + (uint32_t)c4 * 16u;
                cp16(dst, src + (size_t)(base + r) * K + k0 + c4 * 8);
            }
        } else {
#pragma unroll
            for (int i = 0; i < 8; ++i) {
                int id  = i * 256 + tid;
                int mat = id >> 10;
                const uint16_t* src = mat ? Bhi : Ahi;
                int base = mat ? col0 : row0;
                int r  = (id >> 3) & 127;
                int c4 = id & 7;
                uint32_t dst = sbase + (uint32_t)(mat * MATW + r * KPWv) * 4u
                             + (uint32_t)c4 * 16u;
                cp16(dst, src + (size_t)(base + r) * K + k0 + c4 * 8);
            }
        }
    };

    float acc[2][8][4];
#pragma unroll
    for (int mt = 0; mt < 2; ++mt)
#pragma unroll
        for (int nt = 0; nt < 8; ++nt)
#pragma unroll
            for (int q = 0; q < 4; ++q) acc[mt][nt][q] = 0.f;

    load_chunk(0, 0); cp_commit();
    if (NC > 1) load_chunk(1, 1);
    cp_commit();

#pragma unroll 1
    for (int c = 0; c < NC; ++c) {
        const int s = c % NSTG;
        cp_wait1();
        __syncthreads();

        const uint32_t stage = smb + (uint32_t)(s * STW) * 4u;
        const uint32_t aAh = stage + laneA_off;
        const uint32_t aAl = aAh + (uint32_t)MATW * 4u;
        const uint32_t aBh = stage + bBase + laneB_off;
        const uint32_t aBl = aBh + (uint32_t)MATW * 4u;

#pragma unroll
        for (int ks = 0; ks < NKS; ++ks) {
            const uint32_t ko = (uint32_t)ks * 32u;
            uint32_t ah[2][4], al[2][4];
#pragma unroll
            for (int mt = 0; mt < 2; ++mt) {
                ldsm4(ah[mt][0], ah[mt][1], ah[mt][2], ah[mt][3],
                      aAh + (uint32_t)(mt * 16 * KPWv) * 4u + ko);
                if (V == 0)
                    ldsm4(al[mt][0], al[mt][1], al[mt][2], al[mt][3],
                          aAl + (uint32_t)(mt * 16 * KPWv) * 4u + ko);
            }
#pragma unroll
            for (int p = 0; p < 4; ++p) {
                uint32_t bh0, bh1, bh2, bh3;
                ldsm4(bh0, bh1, bh2, bh3, aBh + (uint32_t)(p * 16 * KPWv) * 4u + ko);
                if (V == 0) {
                    uint32_t bl0, bl1, bl2, bl3;
                    ldsm4(bl0, bl1, bl2, bl3, aBl + (uint32_t)(p * 16 * KPWv) * 4u + ko);
#pragma unroll
                    for (int mt = 0; mt < 2; ++mt) {
                        float* ae = acc[mt][2 * p];
                        float* ao = acc[mt][2 * p + 1];
                        mma_bf(ae[0], ae[1], ae[2], ae[3],
                               ah[mt][0], ah[mt][1], ah[mt][2], ah[mt][3], bh0, bh1);
                        mma_bf(ao[0], ao[1], ao[2], ao[3],
                               ah[mt][0], ah[mt][1], ah[mt][2], ah[mt][3], bh2, bh3);
                        mma_bf(ae[0], ae[1], ae[2], ae[3],
                               ah[mt][0], ah[mt][1], ah[mt][2], ah[mt][3], bl0, bl1);
                        mma_bf(ao[0], ao[1], ao[2], ao[3],
                               ah[mt][0], ah[mt][1], ah[mt][2], ah[mt][3], bl2, bl3);
                        mma_bf(ae[0], ae[1], ae[2], ae[3],
                               al[mt][0], al[mt][1], al[mt][2], al[mt][3], bh0, bh1);
                        mma_bf(ao[0], ao[1], ao[2], ao[3],
                               al[mt][0], al[mt][1], al[mt][2], al[mt][3], bh2, bh3);
                    }
                } else {
#pragma unroll
                    for (int mt = 0; mt < 2; ++mt) {
                        float* ae = acc[mt][2 * p];
                        float* ao = acc[mt][2 * p + 1];
                        mma_fp(ae[0], ae[1], ae[2], ae[3],
                               ah[mt][0], ah[mt][1], ah[mt][2], ah[mt][3], bh0, bh1);
                        mma_fp(ao[0], ao[1], ao[2], ao[3],
                               ah[mt][0], ah[mt][1], ah[mt][2], ah[mt][3], bh2, bh3);
                    }
                }
            }
        }
        __syncthreads();
        if (c + 2 < NC) load_chunk(c + 2, (c + 2) % NSTG);
        cp_commit();
    }

    // ---- epilogue ----
#pragma unroll
    for (int mt = 0; mt < 2; ++mt) {
#pragma unroll
        for (int nt = 0; nt < 8; ++nt) {
            int row = row0 + wm * 32 + mt * 16 + gid;
            int col = col0 + wn * 64 + nt * 8 + tig * 2;
            float v0 = acc[mt][nt][0], v1 = acc[mt][nt][1];
            float v2 = acc[mt][nt][2], v3 = acc[mt][nt][3];
            if (mode == 2 || mode == 3 || mode == 5) {
                float b0 = bias[col], b1 = bias[col + 1];
                v0 += b0; v1 += b1; v2 += b0; v3 += b1;
            }
            size_t ad0 = (size_t)row * N + col;
            size_t ad1 = (size_t)(row + 8) * N + col;
            if (mode == 2) {
                bf16* o0 = (bf16*)C0v + zC;
                bf16* o1 = (bf16*)C1v + zC;
                bf16 h0 = __float2bfloat16(v0), h1 = __float2bfloat16(v1);
                bf16 h2 = __float2bfloat16(v2), h3 = __float2bfloat16(v3);
                __nv_bfloat162 hh0 = { h0, h1 }, hh1 = { h2, h3 };
                __nv_bfloat162 ll0 = { __float2bfloat16(v0 - __bfloat162float(h0)),
                                       __float2bfloat16(v1 - __bfloat162float(h1)) };
                __nv_bfloat162 ll1 = { __float2bfloat16(v2 - __bfloat162float(h2)),
                                       __float2bfloat16(v3 - __bfloat162float(h3)) };
                *(__nv_bfloat162*)(o0 + ad0) = hh0;  *(__nv_bfloat162*)(o0 + ad1) = hh1;
                *(__nv_bfloat162*)(o1 + ad0) = ll0;  *(__nv_bfloat162*)(o1 + ad1) = ll1;
            } else if (mode == 4 || mode == 5) {
                fp16* o = (fp16*)C0v + zC;
                __half2 q0 = { __float2half(v0), __float2half(v1) };
                __half2 q1 = { __float2half(v2), __float2half(v3) };
                *(__half2*)(o + ad0) = q0;  *(__half2*)(o + ad1) = q1;
            } else {
                float* o = (float*)C0v + zC;
                float2 q0 = { v0, v1 }, q1 = { v2, v3 };
                *(float2*)(o + ad0) = q0;  *(float2*)(o + ad1) = q1;
            }
        }
    }
}

// ---------------- prep / softmax / reduce -----------------------------------
__global__ void copy_bias2(const float* __restrict__ b0, const float* __restrict__ b1,
                           float* __restrict__ dst)
{
    int i = threadIdx.x;
    dst[i] = b0[i];
    dst[CD + i] = b1[i];
}
__global__ void split_transpose_x(const float* __restrict__ x, bf16* __restrict__ xhi,
                                  bf16* __restrict__ xlo, fp16* __restrict__ xTh)
{
    __shared__ float t[32][33];
    int c0 = blockIdx.x * 32, r0 = blockIdx.y * 32;
    int tx = threadIdx.x, ty = threadIdx.y;
#pragma unroll
    for (int i = 0; i < 4; ++i) {
        size_t ad = (size_t)(r0 + ty + i*8) * CD + c0 + tx;
        float v = x[ad];
        t[ty + i*8][tx] = v;
        bf16 h = __float2bfloat16(v);
        xhi[ad] = h;
        xlo[ad] = __float2bfloat16(v - __bfloat162float(h));
    }
    __syncthreads();
#pragma unroll
    for (int i = 0; i < 4; ++i) {
        size_t ad = (size_t)(c0 + ty + i*8) * NTOK + r0 + tx;
        xTh[ad] = __float2half(t[tx][ty + i*8]);
    }
}
__global__ void transpose_split_bf2(const float* __restrict__ W0, const float* __restrict__ W1,
                                    bf16* __restrict__ dhi, bf16* __restrict__ dlo)
{
    __shared__ float t[32][33];
    const float* s = blockIdx.z ? W1 : W0;
    bf16* oh = dhi + (size_t)blockIdx.z * CD * CD;
    bf16* ol = dlo + (size_t)blockIdx.z * CD * CD;
    int c0 = blockIdx.x * 32, r0 = blockIdx.y * 32;
    int tx = threadIdx.x, ty = threadIdx.y;
#pragma unroll
    for (int i = 0; i < 4; ++i)
        t[ty + i*8][tx] = s[(size_t)(r0 + ty + i*8) * CD + c0 + tx];
    __syncthreads();
#pragma unroll
    for (int i = 0; i < 4; ++i) {
        float v = t[tx][ty + i*8];
        bf16 h = __float2bfloat16(v);
        size_t ad = (size_t)(c0 + ty + i*8) * CD + r0 + tx;
        oh[ad] = h;
        ol[ad] = __float2bfloat16(v - __bfloat162float(h));
    }
}
__global__ void transpose_fp16(const float* __restrict__ src, fp16* __restrict__ dst,
                               int R, int C)
{
    __shared__ float t[32][33];
    const size_t bo = (size_t)blockIdx.z * R * C;
    const float* s = src + bo;
    fp16* o = dst + bo;
    int c0 = blockIdx.x * 32, r0 = blockIdx.y * 32;
    int tx = threadIdx.x, ty = threadIdx.y;
#pragma unroll
    for (int i = 0; i < 4; ++i)
        t[ty + i*8][tx] = s[(size_t)(r0 + ty + i*8) * C + c0 + tx];
    __syncthreads();
#pragma unroll
    for (int i = 0; i < 4; ++i) {
        size_t ad = (size_t)(c0 + ty + i*8) * R + r0 + tx;
        o[ad] = __float2half(t[tx][ty + i*8]);
    }
}
__device__ __forceinline__ float wmax(float v) {
#pragma unroll
    for (int o = 16; o > 0; o >>= 1) v = fmaxf(v, __shfl_xor_sync(0xffffffffu, v, o));
    return v;
}
__device__ __forceinline__ float wsum(float v) {
#pragma unroll
    for (int o = 16; o > 0; o >>= 1) v += __shfl_xor_sync(0xffffffffu, v, o);
    return v;
}
__global__ __launch_bounds__(256, 4)
void softmax_fp16(const float* __restrict__ S, fp16* __restrict__ Phi)
{
    const float* r = S + (size_t)blockIdx.x * NTOK;
    fp16* ph = Phi + (size_t)blockIdx.x * NTOK;
    const int tid = threadIdx.x;
    __shared__ float red[8];
    float v[32];
    float m = -3.4e38f;
#pragma unroll
    for (int i = 0; i < 32; ++i) { v[i] = r[i*256 + tid]; m = fmaxf(m, v[i]); }
    m = wmax(m);
    if ((tid & 31) == 0) red[tid >> 5] = m;
    __syncthreads();
    { float t = red[tid & 7];
      t = fmaxf(t, __shfl_xor_sync(0xffffffffu, t, 1));
      t = fmaxf(t, __shfl_xor_sync(0xffffffffu, t, 2));
      t = fmaxf(t, __shfl_xor_sync(0xffffffffu, t, 4)); m = t; }
    float s = 0.f;
#pragma unroll
    for (int i = 0; i < 32; ++i) { v[i] = __expf(v[i] - m); s += v[i]; }
    s = wsum(s);
    __syncthreads();
    if ((tid & 31) == 0) red[tid >> 5] = s;
    __syncthreads();
    { float t = red[tid & 7];
      t += __shfl_xor_sync(0xffffffffu, t, 1);
      t += __shfl_xor_sync(0xffffffffu, t, 2);
      t += __shfl_xor_sync(0xffffffffu, t, 4); s = t; }
    const float inv = 1.f / s;
#pragma unroll
    for (int i = 0; i < 32; ++i)
        ph[i*256 + tid] = __float2half(v[i] * inv);
}
__global__ void reduce_heads(const fp16* __restrict__ Z, float* __restrict__ out)
{
    const size_t n = (size_t)NTOK * CD / 4;
    const size_t str = n;
    const uint2* z = (const uint2*)Z;
    for (size_t i = (size_t)blockIdx.x * blockDim.x + threadIdx.x; i < n;
         i += (size_t)gridDim.x * blockDim.x) {
        float4 a = { 0.f, 0.f, 0.f, 0.f };
#pragma unroll
        for (int h = 0; h < NH; ++h) {
            uint2 u = z[h * str + i];
            float2 p0 = __half22float2(*(const __half2*)&u.x);
            float2 p1 = __half22float2(*(const __half2*)&u.y);
            a.x += fmaxf(p0.x, 0.f); a.y += fmaxf(p0.y, 0.f);
            a.z += fmaxf(p1.x, 0.f); a.w += fmaxf(p1.y, 0.f);
        }
        a.x *= 0.125f; a.y *= 0.125f; a.z *= 0.125f; a.w *= 0.125f;
        ((float4*)out)[i] = a;
    }
}

// ---------------- host -------------------------------------------------------
extern "C" void kernel_launch(void* const* d_in, const int* in_sizes, int n_in,
                              void* d_out, int out_size)
{
    (void)in_sizes; (void)n_in; (void)out_size;
    const float* x  = (const float*)d_in[0];
    const float* Wt = (const float*)d_in[1];
    const float* bt = (const float*)d_in[2];
    const float* Wp = (const float*)d_in[3];
    const float* bp = (const float*)d_in[4];
    const float* Wk = (const float*)d_in[5];
    const float* bk = (const float*)d_in[6];
    float* out = (float*)d_out;

    bf16 *xhi,*xlo,*WThi,*WTlo,*QKhi,*QKlo;
    fp16 *xTh,*WkTh,*Phi,*Yh,*Z;
    float *S,*bias2;
    cudaGetSymbolAddress((void**)&xhi, g_xhi);   cudaGetSymbolAddress((void**)&xlo, g_xlo);
    cudaGetSymbolAddress((void**)&WThi, g_WThi); cudaGetSymbolAddress((void**)&WTlo, g_WTlo);
    cudaGetSymbolAddress((void**)&QKhi, g_QKhi); cudaGetSymbolAddress((void**)&QKlo, g_QKlo);
    cudaGetSymbolAddress((void**)&bias2, g_bias2);
    cudaGetSymbolAddress((void**)&xTh, g_xTh);   cudaGetSymbolAddress((void**)&WkTh, g_WkTh);
    cudaGetSymbolAddress((void**)&Phi, g_Phi);   cudaGetSymbolAddress((void**)&Yh, g_Yh);
    cudaGetSymbolAddress((void**)&S, g_S);       cudaGetSymbolAddress((void**)&Z, g_Z);

    cudaFuncSetAttribute(gemm_tc<0>, cudaFuncAttributeMaxDynamicSharedMemorySize, SMEM_V0);
    cudaFuncSetAttribute(gemm_tc<2>, cudaFuncAttributeMaxDynamicSharedMemorySize, SMEM_V2);

    // prep
    copy_bias2<<<1, CD>>>(bt, bp, bias2);
    split_transpose_x<<<dim3(CD/32, NTOK/32), dim3(32, 8)>>>(x, xhi, xlo, xTh);
    transpose_split_bf2<<<dim3(CD/32, CD/32, 2), dim3(32, 8)>>>(Wt, Wp, WThi, WTlo);
    transpose_fp16<<<dim3(CD/32, CD/32, NH), dim3(32, 8)>>>(Wk, WkTh, CD, CD);

    const int mt = NTOK / BM;            // 64
    const size_t QKstr = (size_t)NTOK * CD;
    // Q and K projections fused: z=0 -> Q (Wt, bt), z=1 -> K (Wp, bp)
    gemm_tc<0><<<dim3(mt * (CD/BN), 1, 2), 256, SMEM_V0>>>(
        (const uint16_t*)xhi, (const uint16_t*)xlo,
        (const uint16_t*)WThi, (const uint16_t*)WTlo,
        CD, CD, QKhi, QKlo, bias2, 2,
        (size_t)CD * CD, (size_t)CD, QKstr);
    // sim (bf16x3, fp32 out): A = Q, B = K
    gemm_tc<0><<<mt * (NTOK/BN), 256, SMEM_V0>>>(
        (const uint16_t*)QKhi, (const uint16_t*)QKlo,
        (const uint16_t*)(QKhi + QKstr), (const uint16_t*)(QKlo + QKstr),
        CD, NTOK, S, nullptr, nullptr, 0, 0, 0, 0);
    // softmax -> fp16 P
    softmax_fp16<<<NTOK, 256>>>(S, Phi);
    // Y = P @ x (fp16 single pass, BK=64, 3 stages, fp16 out)
    gemm_tc<2><<<mt * (CD/BN), 256, SMEM_V2>>>(
        (const uint16_t*)Phi, nullptr,
        (const uint16_t*)xTh, nullptr,
        NTOK, CD, Yh, nullptr, nullptr, 4, 0, 0, 0);
    // Z[h] = Y @ Wk[h]^T + bk[h] (fp16 single pass, BK=64, 3 stages, fp16 out)
    gemm_tc<2><<<dim3(mt * (CD/BN), 1, NH), 256, SMEM_V2>>>(
        (const uint16_t*)Yh, nullptr,
        (const uint16_t*)WkTh, nullptr,
        CD, CD, Z, nullptr, bk, 5,
        (size_t)CD * CD, (size_t)CD, (size_t)NTOK * CD);
    // out = mean_h relu(Z)
    reduce_heads<<<512, 256>>>(Z, out);
}

// round 17
// speedup vs baseline: 1.1243x; 1.0090x over previous
#include <cuda_runtime.h>
#include <cuda_bf16.h>
#include <cuda_fp16.h>
#include <cstdint>
#include <cstddef>

#define NTOK 8192
#define CD   512
#define NH   8

#define BM 128
#define BN 128

typedef __nv_bfloat16 bf16;
typedef __half fp16;

// V0 (bf16x3): BK=32, KPW=20, 2 stages;  V2 (fp16 single): BK=64, KPW=36, 3 stages
#define SMEM_V0 (2 * 4 * (128 * 20) * 4)     // 81920
#define SMEM_V2 (3 * 2 * (128 * 36) * 4)     // 110592

// ---------------- scratch ----------------------------------------------------
__device__ bf16 g_xhi[NTOK*CD],  g_xlo[NTOK*CD];
__device__ bf16 g_Whi[2*CD*CD],  g_Wlo[2*CD*CD];      // Wtheta, Wphi row-major splits
__device__ bf16 g_MThi[CD*CD],   g_MTlo[CD*CD];       // (Wphi Wtheta^T) split
__device__ bf16 g_Ghi[NTOK*CD],  g_Glo[NTOK*CD];      // G = x M split
__device__ float g_w[CD];
__device__ float g_v[NTOK];
__device__ fp16 g_xTh[CD*NTOK];
__device__ fp16 g_WkTh[NH*CD*CD];
__device__ fp16 g_Phi[(size_t)NTOK*NTOK];
__device__ fp16 g_Yh[NTOK*CD];
__device__ float g_S[(size_t)NTOK*NTOK];
__device__ fp16 g_Z[(size_t)NH*NTOK*CD];

// ---------------- helpers ----------------------------------------------------
__device__ __forceinline__ uint32_t smem_u32(const void* p) {
    uint32_t a;
    asm("{ .reg .u64 t; cvta.to.shared.u64 t, %1; cvt.u32.u64 %0, t; }" : "=r"(a) : "l"(p));
    return a;
}
__device__ __forceinline__ void cp16(uint32_t d, const void* s) {
    asm volatile("cp.async.cg.shared.global [%0], [%1], 16;" :: "r"(d), "l"(s));
}
__device__ __forceinline__ void cp_commit() { asm volatile("cp.async.commit_group;"); }
__device__ __forceinline__ void cp_wait1()  { asm volatile("cp.async.wait_group 1;"); }

__device__ __forceinline__ void ldsm4(uint32_t& r0, uint32_t& r1, uint32_t& r2, uint32_t& r3,
                                      uint32_t addr) {
    asm volatile("ldmatrix.sync.aligned.m8n8.x4.shared.b16 {%0,%1,%2,%3}, [%4];"
                 : "=r"(r0), "=r"(r1), "=r"(r2), "=r"(r3) : "r"(addr));
}
__device__ __forceinline__ void mma_bf(float& c0, float& c1, float& c2, float& c3,
                                       uint32_t a0, uint32_t a1, uint32_t a2, uint32_t a3,
                                       uint32_t b0, uint32_t b1) {
    asm volatile(
        "mma.sync.aligned.m16n8k16.row.col.f32.bf16.bf16.f32 "
        "{%0,%1,%2,%3}, {%4,%5,%6,%7}, {%8,%9}, {%0,%1,%2,%3};"
        : "+f"(c0), "+f"(c1), "+f"(c2), "+f"(c3)
        : "r"(a0), "r"(a1), "r"(a2), "r"(a3), "r"(b0), "r"(b1));
}
__device__ __forceinline__ void mma_fp(float& c0, float& c1, float& c2, float& c3,
                                       uint32_t a0, uint32_t a1, uint32_t a2, uint32_t a3,
                                       uint32_t b0, uint32_t b1) {
    asm volatile(
        "mma.sync.aligned.m16n8k16.row.col.f32.f16.f16.f32 "
        "{%0,%1,%2,%3}, {%4,%5,%6,%7}, {%8,%9}, {%0,%1,%2,%3};"
        : "+f"(c0), "+f"(c1), "+f"(c2), "+f"(c3)
        : "r"(a0), "r"(a1), "r"(a2), "r"(a3), "r"(b0), "r"(b1));
}

// ---------------- tensor GEMM: C[Mr, N] = A @ B^T ----------------------------
// V=0: bf16x3 (A hi/lo mats 0/1, B hi/lo mats 2/3), BK=32, KPW=20, 2 stages
// V=2: fp16 single-pass (A mat 0, B mat 1), BK=64, KPW=36, 3 stages
// mode 0: fp32->C0  1: split bf16->C0/C1  2: +bias split bf16->C0/C1
// mode 3: +bias fp32->C0  4: fp16->C0  5: +bias fp16->C0
template<int V>
__global__ __launch_bounds__(256, 2)
void gemm_tc(const uint16_t* __restrict__ Ahi, const uint16_t* __restrict__ Alo,
             const uint16_t* __restrict__ Bhi, const uint16_t* __restrict__ Blo,
             int Mr, int K, int N, void* __restrict__ C0v, void* __restrict__ C1v,
             const float* __restrict__ bias, int mode,
             size_t strB, size_t strBias, size_t strC)
{
    constexpr int KPWv  = (V == 0) ? 20 : 36;
    constexpr int BKv   = (V == 0) ? 32 : 64;
    constexpr int NKS   = BKv / 16;
    constexpr int MATW  = 128 * KPWv;
    constexpr int STW   = ((V == 0) ? 4 : 2) * MATW;
    constexpr int NSTG  = (V == 0) ? 2 : 3;

    extern __shared__ float sm[];
    const int tid  = threadIdx.x;
    const int wid  = tid >> 5, lane = tid & 31;
    const int gid  = lane >> 2, tig = lane & 3;
    const int wm   = wid & 3, wn = wid >> 2;

    const int z = blockIdx.z;
    Bhi += (size_t)z * strB;
    if (V == 0) Blo += (size_t)z * strB;
    if (bias) bias += (size_t)z * strBias;
    const size_t zC = (size_t)z * strC;

    const int mt_n = Mr / BM, nt_n = N / BN;
    int tile = blockIdx.x;
    int npg  = 8 * nt_n;
    int grp  = tile / npg;
    int fm   = grp * 8;
    int gsz  = min(mt_n - fm, 8);
    int m_t  = fm + (tile % npg) % gsz;
    int n_t  = (tile % npg) / gsz;
    const int row0 = m_t * BM, col0 = n_t * BN;

    const uint32_t smb = smem_u32(sm);
    const int NC = K / BKv;
    const uint32_t bBase = ((V == 0) ? 2u : 1u) * (uint32_t)MATW * 4u;

    const uint32_t laneA_off = (uint32_t)((wm * 32 + (lane & 15)) * KPWv) * 4u
                             + ((lane >> 4) ? 16u : 0u);
    const uint32_t laneB_off = (uint32_t)((wn * 64 + (lane & 7) + ((lane & 16) ? 8 : 0)) * KPWv) * 4u
                             + (((lane >> 3) & 1) ? 16u : 0u);

    auto load_chunk = [&](int c, int s) {
        const int k0 = c * BKv;
        const uint32_t sbase = smb + (uint32_t)(s * STW) * 4u;
        if (V == 0) {
#pragma unroll
            for (int i = 0; i < 8; ++i) {
                int id  = i * 256 + tid;
                int mat = id >> 9;
                const uint16_t* src = (mat == 0) ? Ahi : (mat == 1) ? Alo
                                    : (mat == 2) ? Bhi : Blo;
                int base = (mat <= 1) ? row0 : col0;
                int r  = (id >> 2) & 127;
                int c4 = id & 3;
                uint32_t dst = sbase + (uint32_t)(mat * MATW + r * KPWv) * 4u
                             + (uint32_t)c4 * 16u;
                cp16(dst, src + (size_t)(base + r) * K + k0 + c4 * 8);
            }
        } else {
#pragma unroll
            for (int i = 0; i < 8; ++i) {
                int id  = i * 256 + tid;
                int mat = id >> 10;
                const uint16_t* src = mat ? Bhi : Ahi;
                int base = mat ? col0 : row0;
                int r  = (id >> 3) & 127;
                int c4 = id & 7;
                uint32_t dst = sbase + (uint32_t)(mat * MATW + r * KPWv) * 4u
                             + (uint32_t)c4 * 16u;
                cp16(dst, src + (size_t)(base + r) * K + k0 + c4 * 8);
            }
        }
    };

    float acc[2][8][4];
#pragma unroll
    for (int mt = 0; mt < 2; ++mt)
#pragma unroll
        for (int nt = 0; nt < 8; ++nt)
#pragma unroll
            for (int q = 0; q < 4; ++q) acc[mt][nt][q] = 0.f;

    load_chunk(0, 0); cp_commit();
    if (NC > 1) load_chunk(1, 1);
    cp_commit();

#pragma unroll 1
    for (int c = 0; c < NC; ++c) {
        const int s = c % NSTG;
        cp_wait1();
        __syncthreads();

        const uint32_t stage = smb + (uint32_t)(s * STW) * 4u;
        const uint32_t aAh = stage + laneA_off;
        const uint32_t aAl = aAh + (uint32_t)MATW * 4u;
        const uint32_t aBh = stage + bBase + laneB_off;
        const uint32_t aBl = aBh + (uint32_t)MATW * 4u;

#pragma unroll
        for (int ks = 0; ks < NKS; ++ks) {
            const uint32_t ko = (uint32_t)ks * 32u;
            uint32_t ah[2][4], al[2][4];
#pragma unroll
            for (int mt = 0; mt < 2; ++mt) {
                ldsm4(ah[mt][0], ah[mt][1], ah[mt][2], ah[mt][3],
                      aAh + (uint32_t)(mt * 16 * KPWv) * 4u + ko);
                if (V == 0)
                    ldsm4(al[mt][0], al[mt][1], al[mt][2], al[mt][3],
                          aAl + (uint32_t)(mt * 16 * KPWv) * 4u + ko);
            }
#pragma unroll
            for (int p = 0; p < 4; ++p) {
                uint32_t bh0, bh1, bh2, bh3;
                ldsm4(bh0, bh1, bh2, bh3, aBh + (uint32_t)(p * 16 * KPWv) * 4u + ko);
                if (V == 0) {
                    uint32_t bl0, bl1, bl2, bl3;
                    ldsm4(bl0, bl1, bl2, bl3, aBl + (uint32_t)(p * 16 * KPWv) * 4u + ko);
#pragma unroll
                    for (int mt = 0; mt < 2; ++mt) {
                        float* ae = acc[mt][2 * p];
                        float* ao = acc[mt][2 * p + 1];
                        mma_bf(ae[0], ae[1], ae[2], ae[3],
                               ah[mt][0], ah[mt][1], ah[mt][2], ah[mt][3], bh0, bh1);
                        mma_bf(ao[0], ao[1], ao[2], ao[3],
                               ah[mt][0], ah[mt][1], ah[mt][2], ah[mt][3], bh2, bh3);
                        mma_bf(ae[0], ae[1], ae[2], ae[3],
                               ah[mt][0], ah[mt][1], ah[mt][2], ah[mt][3], bl0, bl1);
                        mma_bf(ao[0], ao[1], ao[2], ao[3],
                               ah[mt][0], ah[mt][1], ah[mt][2], ah[mt][3], bl2, bl3);
                        mma_bf(ae[0], ae[1], ae[2], ae[3],
                               al[mt][0], al[mt][1], al[mt][2], al[mt][3], bh0, bh1);
                        mma_bf(ao[0], ao[1], ao[2], ao[3],
                               al[mt][0], al[mt][1], al[mt][2], al[mt][3], bh2, bh3);
                    }
                } else {
#pragma unroll
                    for (int mt = 0; mt < 2; ++mt) {
                        float* ae = acc[mt][2 * p];
                        float* ao = acc[mt][2 * p + 1];
                        mma_fp(ae[0], ae[1], ae[2], ae[3],
                               ah[mt][0], ah[mt][1], ah[mt][2], ah[mt][3], bh0, bh1);
                        mma_fp(ao[0], ao[1], ao[2], ao[3],
                               ah[mt][0], ah[mt][1], ah[mt][2], ah[mt][3], bh2, bh3);
                    }
                }
            }
        }
        __syncthreads();
        if (c + 2 < NC) load_chunk(c + 2, (c + 2) % NSTG);
        cp_commit();
    }

    // ---- epilogue ----
#pragma unroll
    for (int mt = 0; mt < 2; ++mt) {
#pragma unroll
        for (int nt = 0; nt < 8; ++nt) {
            int row = row0 + wm * 32 + mt * 16 + gid;
            int col = col0 + wn * 64 + nt * 8 + tig * 2;
            float v0 = acc[mt][nt][0], v1 = acc[mt][nt][1];
            float v2 = acc[mt][nt][2], v3 = acc[mt][nt][3];
            if (mode == 2 || mode == 3 || mode == 5) {
                float b0 = bias[col], b1 = bias[col + 1];
                v0 += b0; v1 += b1; v2 += b0; v3 += b1;
            }
            size_t ad0 = (size_t)row * N + col;
            size_t ad1 = (size_t)(row + 8) * N + col;
            if (mode == 1 || mode == 2) {
                bf16* o0 = (bf16*)C0v + zC;
                bf16* o1 = (bf16*)C1v + zC;
                bf16 h0 = __float2bfloat16(v0), h1 = __float2bfloat16(v1);
                bf16 h2 = __float2bfloat16(v2), h3 = __float2bfloat16(v3);
                __nv_bfloat162 hh0 = { h0, h1 }, hh1 = { h2, h3 };
                __nv_bfloat162 ll0 = { __float2bfloat16(v0 - __bfloat162float(h0)),
                                       __float2bfloat16(v1 - __bfloat162float(h1)) };
                __nv_bfloat162 ll1 = { __float2bfloat16(v2 - __bfloat162float(h2)),
                                       __float2bfloat16(v3 - __bfloat162float(h3)) };
                *(__nv_bfloat162*)(o0 + ad0) = hh0;  *(__nv_bfloat162*)(o0 + ad1) = hh1;
                *(__nv_bfloat162*)(o1 + ad0) = ll0;  *(__nv_bfloat162*)(o1 + ad1) = ll1;
            } else if (mode == 4 || mode == 5) {
                fp16* o = (fp16*)C0v + zC;
                __half2 q0 = { __float2half(v0), __float2half(v1) };
                __half2 q1 = { __float2half(v2), __float2half(v3) };
                *(__half2*)(o + ad0) = q0;  *(__half2*)(o + ad1) = q1;
            } else {
                float* o = (float*)C0v + zC;
                float2 q0 = { v0, v1 }, q1 = { v2, v3 };
                *(float2*)(o + ad0) = q0;  *(float2*)(o + ad1) = q1;
            }
        }
    }
}

// ---------------- prep / softmax / reduce -----------------------------------
// row-major bf16 split of Wtheta (z=0) and Wphi (z=1) into paired arrays
__global__ void split_bf2(const float* __restrict__ W0, const float* __restrict__ W1,
                          bf16* __restrict__ dhi, bf16* __restrict__ dlo)
{
    const float* s = blockIdx.z ? W1 : W0;
    bf16* oh = dhi + (size_t)blockIdx.z * CD * CD;
    bf16* ol = dlo + (size_t)blockIdx.z * CD * CD;
    const int n = CD * CD;
    for (int i = blockIdx.x * blockDim.x + threadIdx.x; i < n; i += gridDim.x * blockDim.x) {
        float v = s[i];
        bf16 h = __float2bfloat16(v);
        oh[i] = h;
        ol[i] = __float2bfloat16(v - __bfloat162float(h));
    }
}
__global__ void split_transpose_x(const float* __restrict__ x, bf16* __restrict__ xhi,
                                  bf16* __restrict__ xlo, fp16* __restrict__ xTh)
{
    __shared__ float t[32][33];
    int c0 = blockIdx.x * 32, r0 = blockIdx.y * 32;
    int tx = threadIdx.x, ty = threadIdx.y;
#pragma unroll
    for (int i = 0; i < 4; ++i) {
        size_t ad = (size_t)(r0 + ty + i*8) * CD + c0 + tx;
        float v = x[ad];
        t[ty + i*8][tx] = v;
        bf16 h = __float2bfloat16(v);
        xhi[ad] = h;
        xlo[ad] = __float2bfloat16(v - __bfloat162float(h));
    }
    __syncthreads();
#pragma unroll
    for (int i = 0; i < 4; ++i) {
        size_t ad = (size_t)(c0 + ty + i*8) * NTOK + r0 + tx;
        xTh[ad] = __float2half(t[tx][ty + i*8]);
    }
}
__global__ void transpose_fp16(const float* __restrict__ src, fp16* __restrict__ dst,
                               int R, int C)
{
    __shared__ float t[32][33];
    const size_t bo = (size_t)blockIdx.z * R * C;
    const float* s = src + bo;
    fp16* o = dst + bo;
    int c0 = blockIdx.x * 32, r0 = blockIdx.y * 32;
    int tx = threadIdx.x, ty = threadIdx.y;
#pragma unroll
    for (int i = 0; i < 4; ++i)
        t[ty + i*8][tx] = s[(size_t)(r0 + ty + i*8) * C + c0 + tx];
    __syncthreads();
#pragma unroll
    for (int i = 0; i < 4; ++i) {
        size_t ad = (size_t)(c0 + ty + i*8) * R + r0 + tx;
        o[ad] = __float2half(t[tx][ty + i*8]);
    }
}
__device__ __forceinline__ float wmax(float v) {
#pragma unroll
    for (int o = 16; o > 0; o >>= 1) v = fmaxf(v, __shfl_xor_sync(0xffffffffu, v, o));
    return v;
}
__device__ __forceinline__ float wsum(float v) {
#pragma unroll
    for (int o = 16; o > 0; o >>= 1) v += __shfl_xor_sync(0xffffffffu, v, o);
    return v;
}
// w[e] = dot(Wphi[e, :], btheta)   (grid*8 warps, warp per row)
__global__ void gemv_w(const float* __restrict__ Wp, const float* __restrict__ bt,
                       float* __restrict__ w)
{
    int warp = (blockIdx.x * blockDim.x + threadIdx.x) >> 5;
    int lane = threadIdx.x & 31;
    if (warp >= CD) return;
    const float* r = Wp + (size_t)warp * CD;
    float s = 0.f;
#pragma unroll
    for (int i = 0; i < CD / 32; ++i) s += r[i * 32 + lane] * bt[i * 32 + lane];
    s = wsum(s);
    if (lane == 0) w[warp] = s;
}
// v[j] = dot(x[j, :], w)
__global__ void gemv_v(const float* __restrict__ x, const float* __restrict__ w,
                       float* __restrict__ v)
{
    int warp = (blockIdx.x * blockDim.x + threadIdx.x) >> 5;
    int lane = threadIdx.x & 31;
    if (warp >= NTOK) return;
    const float* r = x + (size_t)warp * CD;
    float s = 0.f;
#pragma unroll
    for (int i = 0; i < CD / 32; ++i) s += r[i * 32 + lane] * w[i * 32 + lane];
    s = wsum(s);
    if (lane == 0) v[warp] = s;
}
__global__ __launch_bounds__(256, 4)
void softmax_fp16(const float* __restrict__ S, const float* __restrict__ vcol,
                  fp16* __restrict__ Phi)
{
    const float* r = S + (size_t)blockIdx.x * NTOK;
    fp16* ph = Phi + (size_t)blockIdx.x * NTOK;
    const int tid = threadIdx.x;
    __shared__ float red[8];
    float v[32];
    float m = -3.4e38f;
#pragma unroll
    for (int i = 0; i < 32; ++i) {
        v[i] = r[i*256 + tid] + vcol[i*256 + tid];
        m = fmaxf(m, v[i]);
    }
    m = wmax(m);
    if ((tid & 31) == 0) red[tid >> 5] = m;
    __syncthreads();
    { float t = red[tid & 7];
      t = fmaxf(t, __shfl_xor_sync(0xffffffffu, t, 1));
      t = fmaxf(t, __shfl_xor_sync(0xffffffffu, t, 2));
      t = fmaxf(t, __shfl_xor_sync(0xffffffffu, t, 4)); m = t; }
    float s = 0.f;
#pragma unroll
    for (int i = 0; i < 32; ++i) { v[i] = __expf(v[i] - m); s += v[i]; }
    s = wsum(s);
    __syncthreads();
    if ((tid & 31) == 0) red[tid >> 5] = s;
    __syncthreads();
    { float t = red[tid & 7];
      t += __shfl_xor_sync(0xffffffffu, t, 1);
      t += __shfl_xor_sync(0xffffffffu, t, 2);
      t += __shfl_xor_sync(0xffffffffu, t, 4); s = t; }
    const float inv = 1.f / s;
#pragma unroll
    for (int i = 0; i < 32; ++i)
        ph[i*256 + tid] = __float2half(v[i] * inv);
}
__global__ void reduce_heads(const fp16* __restrict__ Z, float* __restrict__ out)
{
    const size_t n = (size_t)NTOK * CD / 4;
    const size_t str = n;
    const uint2* z = (const uint2*)Z;
    for (size_t i = (size_t)blockIdx.x * blockDim.x + threadIdx.x; i < n;
         i += (size_t)gridDim.x * blockDim.x) {
        float4 a = { 0.f, 0.f, 0.f, 0.f };
#pragma unroll
        for (int h = 0; h < NH; ++h) {
            uint2 u = z[h * str + i];
            float2 p0 = __half22float2(*(const __half2*)&u.x);
            float2 p1 = __half22float2(*(const __half2*)&u.y);
            a.x += fmaxf(p0.x, 0.f); a.y += fmaxf(p0.y, 0.f);
            a.z += fmaxf(p1.x, 0.f); a.w += fmaxf(p1.y, 0.f);
        }
        a.x *= 0.125f; a.y *= 0.125f; a.z *= 0.125f; a.w *= 0.125f;
        ((float4*)out)[i] = a;
    }
}

// ---------------- host -------------------------------------------------------
extern "C" void kernel_launch(void* const* d_in, const int* in_sizes, int n_in,
                              void* d_out, int out_size)
{
    (void)in_sizes; (void)n_in; (void)out_size;
    const float* x  = (const float*)d_in[0];
    const float* Wt = (const float*)d_in[1];
    const float* bt = (const float*)d_in[2];
    const float* Wp = (const float*)d_in[3];
    const float* bp = (const float*)d_in[4];
    const float* Wk = (const float*)d_in[5];
    const float* bk = (const float*)d_in[6];
    (void)bp;  // row-uniform terms cancel in softmax
    float* out = (float*)d_out;

    bf16 *xhi,*xlo,*Whi,*Wlo,*MThi,*MTlo,*Ghi,*Glo;
    fp16 *xTh,*WkTh,*Phi,*Yh,*Z;
    float *S,*wv,*vv;
    cudaGetSymbolAddress((void**)&xhi, g_xhi);   cudaGetSymbolAddress((void**)&xlo, g_xlo);
    cudaGetSymbolAddress((void**)&Whi, g_Whi);   cudaGetSymbolAddress((void**)&Wlo, g_Wlo);
    cudaGetSymbolAddress((void**)&MThi, g_MThi); cudaGetSymbolAddress((void**)&MTlo, g_MTlo);
    cudaGetSymbolAddress((void**)&Ghi, g_Ghi);   cudaGetSymbolAddress((void**)&Glo, g_Glo);
    cudaGetSymbolAddress((void**)&wv, g_w);      cudaGetSymbolAddress((void**)&vv, g_v);
    cudaGetSymbolAddress((void**)&xTh, g_xTh);   cudaGetSymbolAddress((void**)&WkTh, g_WkTh);
    cudaGetSymbolAddress((void**)&Phi, g_Phi);   cudaGetSymbolAddress((void**)&Yh, g_Yh);
    cudaGetSymbolAddress((void**)&S, g_S);       cudaGetSymbolAddress((void**)&Z, g_Z);

    cudaFuncSetAttribute(gemm_tc<0>, cudaFuncAttributeMaxDynamicSharedMemorySize, SMEM_V0);
    cudaFuncSetAttribute(gemm_tc<2>, cudaFuncAttributeMaxDynamicSharedMemorySize, SMEM_V2);

    // prep
    split_bf2<<<dim3(128, 1, 2), 256>>>(Wt, Wp, Whi, Wlo);
    split_transpose_x<<<dim3(CD/32, NTOK/32), dim3(32, 8)>>>(x, xhi, xlo, xTh);
    transpose_fp16<<<dim3(CD/32, CD/32, NH), dim3(32, 8)>>>(Wk, WkTh, CD, CD);
    gemv_w<<<CD / 8, 256>>>(Wp, bt, wv);
    gemv_v<<<NTOK / 8, 256>>>(x, wv, vv);

    const int mt = NTOK / BM;            // 64
    const size_t WW = (size_t)CD * CD;
    // MT = Wphi @ Wtheta^T  (bf16x3, split out, 512x512)
    gemm_tc<0><<<(CD/BM) * (CD/BN), 256, SMEM_V0>>>(
        (const uint16_t*)(Whi + WW), (const uint16_t*)(Wlo + WW),
        (const uint16_t*)Whi, (const uint16_t*)Wlo,
        CD, CD, CD, MThi, MTlo, nullptr, 1, 0, 0, 0);
    // G = x @ MT^T = x M  (bf16x3, split out)
    gemm_tc<0><<<mt * (CD/BN), 256, SMEM_V0>>>(
        (const uint16_t*)xhi, (const uint16_t*)xlo,
        (const uint16_t*)MThi, (const uint16_t*)MTlo,
        NTOK, CD, CD, Ghi, Glo, nullptr, 1, 0, 0, 0);
    // S = G @ x^T  (bf16x3, fp32 out)
    gemm_tc<0><<<mt * (NTOK/BN), 256, SMEM_V0>>>(
        (const uint16_t*)Ghi, (const uint16_t*)Glo,
        (const uint16_t*)xhi, (const uint16_t*)xlo,
        NTOK, CD, NTOK, S, nullptr, nullptr, 0, 0, 0, 0);
    // softmax over rows of S + v (column term) -> fp16 P
    softmax_fp16<<<NTOK, 256>>>(S, vv, Phi);
    // Y = P @ x (fp16 single pass, BK=64, 3 stages, fp16 out)
    gemm_tc<2><<<mt * (CD/BN), 256, SMEM_V2>>>(
        (const uint16_t*)Phi, nullptr,
        (const uint16_t*)xTh, nullptr,
        NTOK, NTOK, CD, Yh, nullptr, nullptr, 4, 0, 0, 0);
    // Z[h] = Y @ Wk[h]^T + bk[h] (fp16 single pass, BK=64, 3 stages, fp16 out)
    gemm_tc<2><<<dim3(mt * (CD/BN), 1, NH), 256, SMEM_V2>>>(
        (const uint16_t*)Yh, nullptr,
        (const uint16_t*)WkTh, nullptr,
        NTOK, CD, CD, Z, nullptr, bk, 5,
        (size_t)CD * CD, (size_t)CD, (size_t)NTOK * CD);
    // out = mean_h relu(Z)
    reduce_heads<<<512, 256>>>(Z, out);
}